// round 1
// baseline (speedup 1.0000x reference)
#include <cuda_runtime.h>
#include <math.h>

#define NB   2
#define NSEQ 2048
#define NC   1024
#define NH   16
#define ND   64

static __device__ __constant__ float ATT_SCALE = 0.125f;  // 64^-0.5

// ---- scratch (device globals; no allocation in kernel_launch) ----
__device__ float g_QQ [(size_t)NB * NH * NSEQ * 2 * ND];   //  33.5 MB  [q+u | q+v]
__device__ float g_KK [(size_t)NB * NH * NSEQ * 2 * ND];   //  33.5 MB  [k | p]
__device__ float g_V  [(size_t)NB * NH * NSEQ * ND];       //  16.8 MB  (B,H,N,D)
__device__ float g_P  [(size_t)NB * NH * NSEQ * NSEQ];     // 536.9 MB  logits/probs
__device__ float g_ctx[(size_t)NB * NSEQ * NC];            //  16.8 MB  (B,N,C)

// ============================================================================
// Projection GEMM: y = x @ W^T (+bias), with layout-transforming epilogues.
// Tile 64x64, BK=16, 256 threads, 4x4 per thread. All dims divide evenly.
// MODE 0: q -> g_QQ[..,0:64]=q+u, g_QQ[..,64:128]=q+v
// MODE 1: k -> g_KK[..,0:64]
// MODE 2: p -> g_KK[..,64:128]   (no bias)
// MODE 3: v -> g_V (B,H,N,D)
// MODE 4: out = g_ctx @ Wo^T + bo  (reads A from g_ctx, writes plain row-major)
// ============================================================================
template <int MODE>
__global__ void __launch_bounds__(256, 2) proj_kernel(
    const float* __restrict__ A, const float* __restrict__ W,
    const float* __restrict__ bias, const float* __restrict__ pbu,
    const float* __restrict__ pbv, float* __restrict__ out)
{
    __shared__ float As[16][68];
    __shared__ float Bs[16][68];
    const int K  = NC;
    const int bm = blockIdx.y * 64;
    const int bn = blockIdx.x * 64;
    const int t  = threadIdx.x;
    const int ty = t >> 4, tx = t & 15;
    const int lr = t >> 2;            // 0..63 tile row for loads
    const int lk = (t & 3) << 2;      // 0,4,8,12 k-offset for loads

    const float* Ap = (MODE == 4) ? g_ctx : A;

    float acc[4][4] = {};
    for (int k0 = 0; k0 < K; k0 += 16) {
        float4 av = *(const float4*)(Ap + (size_t)(bm + lr) * K + k0 + lk);
        float4 bv = *(const float4*)(W  + (size_t)(bn + lr) * K + k0 + lk);
        As[lk + 0][lr] = av.x; As[lk + 1][lr] = av.y;
        As[lk + 2][lr] = av.z; As[lk + 3][lr] = av.w;
        Bs[lk + 0][lr] = bv.x; Bs[lk + 1][lr] = bv.y;
        Bs[lk + 2][lr] = bv.z; Bs[lk + 3][lr] = bv.w;
        __syncthreads();
        #pragma unroll
        for (int kk = 0; kk < 16; kk++) {
            float ra[4], rb[4];
            #pragma unroll
            for (int i = 0; i < 4; i++) ra[i] = As[kk][ty * 4 + i];
            #pragma unroll
            for (int j = 0; j < 4; j++) rb[j] = Bs[kk][tx * 4 + j];
            #pragma unroll
            for (int i = 0; i < 4; i++)
                #pragma unroll
                for (int j = 0; j < 4; j++)
                    acc[i][j] = fmaf(ra[i], rb[j], acc[i][j]);
        }
        __syncthreads();
    }

    #pragma unroll
    for (int i = 0; i < 4; i++) {
        const int row = bm + ty * 4 + i;
        const int b = row >> 11;            // row / NSEQ
        const int n = row & (NSEQ - 1);
        #pragma unroll
        for (int j = 0; j < 4; j++) {
            const int col = bn + tx * 4 + j;
            float val = acc[i][j];
            if (MODE != 2) val += bias[col];
            const int h = col >> 6, d = col & 63;
            if (MODE == 0) {
                const size_t base = (((size_t)(b * NH + h)) * NSEQ + n) * (2 * ND);
                g_QQ[base + d]      = val + pbu[h * ND + d];
                g_QQ[base + ND + d] = val + pbv[h * ND + d];
            } else if (MODE == 1) {
                const size_t base = (((size_t)(b * NH + h)) * NSEQ + n) * (2 * ND);
                g_KK[base + d] = val;
            } else if (MODE == 2) {
                const size_t base = (((size_t)(b * NH + h)) * NSEQ + n) * (2 * ND);
                g_KK[base + ND + d] = val;
            } else if (MODE == 3) {
                g_V[(((size_t)(b * NH + h)) * NSEQ + n) * ND + d] = val;
            } else {
                out[(size_t)row * NC + col] = val;
            }
        }
    }
}

// ============================================================================
// Logits: P[bh] = (QQ[bh] @ KK[bh]^T) * SCALE   -- K = 128 NT GEMM per (b,h)
// ============================================================================
__global__ void __launch_bounds__(256, 2) logits_kernel()
{
    __shared__ float As[16][68];
    __shared__ float Bs[16][68];
    const int bh = blockIdx.z;
    const float* A  = g_QQ + (size_t)bh * NSEQ * 2 * ND;
    const float* Bm = g_KK + (size_t)bh * NSEQ * 2 * ND;
    float* Cp = g_P + (size_t)bh * NSEQ * NSEQ;
    const int K  = 2 * ND;
    const int bm = blockIdx.y * 64;
    const int bn = blockIdx.x * 64;
    const int t  = threadIdx.x;
    const int ty = t >> 4, tx = t & 15;
    const int lr = t >> 2;
    const int lk = (t & 3) << 2;

    float acc[4][4] = {};
    for (int k0 = 0; k0 < K; k0 += 16) {
        float4 av = *(const float4*)(A  + (size_t)(bm + lr) * K + k0 + lk);
        float4 bv = *(const float4*)(Bm + (size_t)(bn + lr) * K + k0 + lk);
        As[lk + 0][lr] = av.x; As[lk + 1][lr] = av.y;
        As[lk + 2][lr] = av.z; As[lk + 3][lr] = av.w;
        Bs[lk + 0][lr] = bv.x; Bs[lk + 1][lr] = bv.y;
        Bs[lk + 2][lr] = bv.z; Bs[lk + 3][lr] = bv.w;
        __syncthreads();
        #pragma unroll
        for (int kk = 0; kk < 16; kk++) {
            float ra[4], rb[4];
            #pragma unroll
            for (int i = 0; i < 4; i++) ra[i] = As[kk][ty * 4 + i];
            #pragma unroll
            for (int j = 0; j < 4; j++) rb[j] = Bs[kk][tx * 4 + j];
            #pragma unroll
            for (int i = 0; i < 4; i++)
                #pragma unroll
                for (int j = 0; j < 4; j++)
                    acc[i][j] = fmaf(ra[i], rb[j], acc[i][j]);
        }
        __syncthreads();
    }

    #pragma unroll
    for (int i = 0; i < 4; i++) {
        const int r = bm + ty * 4 + i;
        #pragma unroll
        for (int j = 0; j < 4; j++)
            Cp[(size_t)r * NSEQ + bn + tx * 4 + j] = acc[i][j] * ATT_SCALE;
    }
}

// ============================================================================
// Row softmax over 2048 columns. One 256-thread block per row, 8 elems/thread.
// ============================================================================
__global__ void __launch_bounds__(256) softmax_kernel()
{
    __shared__ float red[8];
    float* p = g_P + (size_t)blockIdx.x * NSEQ;
    const int t = threadIdx.x;

    float v[8];
    float mx = -1e30f;
    #pragma unroll
    for (int i = 0; i < 8; i++) { v[i] = p[t + i * 256]; mx = fmaxf(mx, v[i]); }
    #pragma unroll
    for (int o = 16; o; o >>= 1) mx = fmaxf(mx, __shfl_xor_sync(0xFFFFFFFFu, mx, o));
    if ((t & 31) == 0) red[t >> 5] = mx;
    __syncthreads();
    mx = red[0];
    #pragma unroll
    for (int w = 1; w < 8; w++) mx = fmaxf(mx, red[w]);
    __syncthreads();

    float s = 0.f;
    #pragma unroll
    for (int i = 0; i < 8; i++) { v[i] = __expf(v[i] - mx); s += v[i]; }
    #pragma unroll
    for (int o = 16; o; o >>= 1) s += __shfl_xor_sync(0xFFFFFFFFu, s, o);
    if ((t & 31) == 0) red[t >> 5] = s;
    __syncthreads();
    s = red[0];
    #pragma unroll
    for (int w = 1; w < 8; w++) s += red[w];
    const float inv = 1.f / s;
    #pragma unroll
    for (int i = 0; i < 8; i++) p[t + i * 256] = v[i] * inv;
}

// ============================================================================
// ctx = P @ V per (b,h): M=2048, N=64, K=2048 (NN GEMM), write ctx (B,N,C)
// ============================================================================
__global__ void __launch_bounds__(256, 2) av_kernel()
{
    __shared__ float As[16][68];
    __shared__ float Bs[16][72];     // padded to keep float4 smem stores aligned
    const int bh = blockIdx.z;
    const float* A  = g_P + (size_t)bh * NSEQ * NSEQ;
    const float* Vp = g_V + (size_t)bh * NSEQ * ND;
    const int bm = blockIdx.y * 64;
    const int t  = threadIdx.x;
    const int ty = t >> 4, tx = t & 15;
    const int lr = t >> 2;
    const int lk = (t & 3) << 2;
    const int kr = t >> 4;           // 0..15
    const int c4 = (t & 15) << 2;    // 0..60

    float acc[4][4] = {};
    for (int k0 = 0; k0 < NSEQ; k0 += 16) {
        float4 av = *(const float4*)(A  + (size_t)(bm + lr) * NSEQ + k0 + lk);
        float4 bv = *(const float4*)(Vp + (size_t)(k0 + kr) * ND + c4);
        As[lk + 0][lr] = av.x; As[lk + 1][lr] = av.y;
        As[lk + 2][lr] = av.z; As[lk + 3][lr] = av.w;
        *(float4*)&Bs[kr][c4] = bv;
        __syncthreads();
        #pragma unroll
        for (int kk = 0; kk < 16; kk++) {
            float ra[4], rb[4];
            #pragma unroll
            for (int i = 0; i < 4; i++) ra[i] = As[kk][ty * 4 + i];
            #pragma unroll
            for (int j = 0; j < 4; j++) rb[j] = Bs[kk][tx * 4 + j];
            #pragma unroll
            for (int i = 0; i < 4; i++)
                #pragma unroll
                for (int j = 0; j < 4; j++)
                    acc[i][j] = fmaf(ra[i], rb[j], acc[i][j]);
        }
        __syncthreads();
    }

    const int b = bh >> 4, h = bh & 15;
    #pragma unroll
    for (int i = 0; i < 4; i++) {
        const int n = bm + ty * 4 + i;
        #pragma unroll
        for (int j = 0; j < 4; j++) {
            const int d = tx * 4 + j;
            g_ctx[((size_t)(b * NSEQ + n)) * NC + h * ND + d] = acc[i][j];
        }
    }
}

// ============================================================================
extern "C" void kernel_launch(void* const* d_in, const int* in_sizes, int n_in,
                              void* d_out, int out_size)
{
    const float* hs   = (const float*)d_in[0];
    const float* pe   = (const float*)d_in[1];
    const float* Wq   = (const float*)d_in[2];
    const float* bq   = (const float*)d_in[3];
    const float* Wk   = (const float*)d_in[4];
    const float* bk   = (const float*)d_in[5];
    const float* Wv   = (const float*)d_in[6];
    const float* bv   = (const float*)d_in[7];
    const float* Wpos = (const float*)d_in[8];
    const float* pbu  = (const float*)d_in[9];
    const float* pbv  = (const float*)d_in[10];
    const float* Wo   = (const float*)d_in[11];
    const float* bo   = (const float*)d_in[12];
    float* out = (float*)d_out;

    const dim3 gproj(NC / 64, (NB * NSEQ) / 64);           // (16, 64)
    proj_kernel<0><<<gproj, 256>>>(hs, Wq, bq, pbu, pbv, nullptr);
    proj_kernel<1><<<gproj, 256>>>(hs, Wk, bk, nullptr, nullptr, nullptr);
    proj_kernel<2><<<gproj, 256>>>(pe, Wpos, nullptr, nullptr, nullptr, nullptr);
    proj_kernel<3><<<gproj, 256>>>(hs, Wv, bv, nullptr, nullptr, nullptr);

    const dim3 glog(NSEQ / 64, NSEQ / 64, NB * NH);        // (32, 32, 32)
    logits_kernel<<<glog, 256>>>();

    softmax_kernel<<<NB * NH * NSEQ, 256>>>();             // 65536 rows

    const dim3 gav(1, NSEQ / 64, NB * NH);                 // (1, 32, 32)
    av_kernel<<<gav, 256>>>();

    proj_kernel<4><<<gproj, 256>>>(nullptr, Wo, bo, nullptr, nullptr, out);
}

// round 2
// speedup vs baseline: 1.1858x; 1.1858x over previous
#include <cuda_runtime.h>
#include <math.h>

#define NB   2
#define NSEQ 2048
#define NC   1024
#define NH   16
#define ND   64
#define ATT_SCALE 0.125f

// ---- scratch (device globals; no allocation in kernel_launch) ----
__device__ float g_QQ [(size_t)NB * NH * NSEQ * 2 * ND];   //  [q+u | q+v]  (B,H,N,128)
__device__ float g_KK [(size_t)NB * NH * NSEQ * 2 * ND];   //  [k | p]      (B,H,N,128)
__device__ float g_V  [(size_t)NB * NH * NSEQ * ND];       //  (B,H,N,D)
__device__ float g_P  [(size_t)NB * NH * NSEQ * NSEQ];     //  logits/probs
__device__ float g_ctx[(size_t)NB * NSEQ * NC];            //  (B,N,C)

// ============================================================================
// Projection GEMM: y = x @ W^T (+bias). Tile 128x64, BK=16, 256 thr, 8x4/thread,
// double-buffered smem. MODE epilogues as in R1.
// ============================================================================
template <int MODE>
__global__ void __launch_bounds__(256, 2) proj_kernel(
    const float* __restrict__ A, const float* __restrict__ W,
    const float* __restrict__ b1, const float* __restrict__ pbu,
    const float* __restrict__ pbv, float* __restrict__ out)
{
    __shared__ float As[2][16][132];
    __shared__ float Bs[2][16][68];

    const float* Ap = (MODE == 4) ? g_ctx : A;
    const int bm = blockIdx.y * 128;
    const int bn = blockIdx.x * 64;
    const int t  = threadIdx.x;
    const int ty = t >> 4, tx = t & 15;
    const int ar = t >> 1, ac = (t & 1) * 8;   // A: 128 rows x 16 cols, 8 floats/thr
    const int br = t >> 2, bc = (t & 3) * 4;   // B:  64 rows x 16 cols, 4 floats/thr

    const float* aptr = Ap + (size_t)(bm + ar) * NC + ac;
    const float* bptr = W  + (size_t)(bn + br) * NC + bc;

    float4 ra0 = *(const float4*)(aptr);
    float4 ra1 = *(const float4*)(aptr + 4);
    float4 rb0 = *(const float4*)(bptr);
    As[0][ac + 0][ar] = ra0.x; As[0][ac + 1][ar] = ra0.y;
    As[0][ac + 2][ar] = ra0.z; As[0][ac + 3][ar] = ra0.w;
    As[0][ac + 4][ar] = ra1.x; As[0][ac + 5][ar] = ra1.y;
    As[0][ac + 6][ar] = ra1.z; As[0][ac + 7][ar] = ra1.w;
    Bs[0][bc + 0][br] = rb0.x; Bs[0][bc + 1][br] = rb0.y;
    Bs[0][bc + 2][br] = rb0.z; Bs[0][bc + 3][br] = rb0.w;
    __syncthreads();

    float acc[8][4] = {};
    const int NIT = NC / 16;
    for (int it = 0; it < NIT; ++it) {
        const int cur = it & 1;
        if (it + 1 < NIT) {
            ra0 = *(const float4*)(aptr + (it + 1) * 16);
            ra1 = *(const float4*)(aptr + (it + 1) * 16 + 4);
            rb0 = *(const float4*)(bptr + (it + 1) * 16);
        }
        #pragma unroll
        for (int kk = 0; kk < 16; kk++) {
            float a[8], b[4];
            *(float4*)(a)     = *(const float4*)&As[cur][kk][ty * 8];
            *(float4*)(a + 4) = *(const float4*)&As[cur][kk][ty * 8 + 4];
            *(float4*)(b)     = *(const float4*)&Bs[cur][kk][tx * 4];
            #pragma unroll
            for (int i = 0; i < 8; i++)
                #pragma unroll
                for (int j = 0; j < 4; j++)
                    acc[i][j] = fmaf(a[i], b[j], acc[i][j]);
        }
        if (it + 1 < NIT) {
            const int nxt = cur ^ 1;
            As[nxt][ac + 0][ar] = ra0.x; As[nxt][ac + 1][ar] = ra0.y;
            As[nxt][ac + 2][ar] = ra0.z; As[nxt][ac + 3][ar] = ra0.w;
            As[nxt][ac + 4][ar] = ra1.x; As[nxt][ac + 5][ar] = ra1.y;
            As[nxt][ac + 6][ar] = ra1.z; As[nxt][ac + 7][ar] = ra1.w;
            Bs[nxt][bc + 0][br] = rb0.x; Bs[nxt][bc + 1][br] = rb0.y;
            Bs[nxt][bc + 2][br] = rb0.z; Bs[nxt][bc + 3][br] = rb0.w;
        }
        __syncthreads();
    }

    // ---- epilogue ----
    const int col0 = bn + tx * 4;
    const int h = col0 >> 6, d = col0 & 63;
    float4 bb = make_float4(0.f, 0.f, 0.f, 0.f);
    if (MODE != 2) bb = *(const float4*)&b1[col0];
    float4 uu, vv;
    if (MODE == 0) {
        uu = *(const float4*)&pbu[h * ND + d];
        vv = *(const float4*)&pbv[h * ND + d];
    }
    #pragma unroll
    for (int i = 0; i < 8; i++) {
        const int row = bm + ty * 8 + i;
        const int b = row >> 11;
        const int n = row & (NSEQ - 1);
        float4 val;
        val.x = acc[i][0] + bb.x; val.y = acc[i][1] + bb.y;
        val.z = acc[i][2] + bb.z; val.w = acc[i][3] + bb.w;
        if (MODE == 0) {
            const size_t base = (((size_t)(b * NH + h)) * NSEQ + n) * (size_t)(2 * ND);
            float4 o1 = make_float4(val.x + uu.x, val.y + uu.y, val.z + uu.z, val.w + uu.w);
            float4 o2 = make_float4(val.x + vv.x, val.y + vv.y, val.z + vv.z, val.w + vv.w);
            *(float4*)&g_QQ[base + d]      = o1;
            *(float4*)&g_QQ[base + ND + d] = o2;
        } else if (MODE == 1) {
            const size_t base = (((size_t)(b * NH + h)) * NSEQ + n) * (size_t)(2 * ND);
            *(float4*)&g_KK[base + d] = val;
        } else if (MODE == 2) {
            const size_t base = (((size_t)(b * NH + h)) * NSEQ + n) * (size_t)(2 * ND);
            *(float4*)&g_KK[base + ND + d] = val;
        } else if (MODE == 3) {
            *(float4*)&g_V[(((size_t)(b * NH + h)) * NSEQ + n) * ND + d] = val;
        } else {
            *(float4*)&out[(size_t)row * NC + col0] = val;
        }
    }
}

// ============================================================================
// Logits: P[bh] = (QQ[bh] @ KK[bh]^T) * SCALE. Tile 128x128, BK=8, 8x8/thread.
// ============================================================================
__global__ void __launch_bounds__(256, 2) logits_kernel()
{
    __shared__ float As[2][8][132];
    __shared__ float Bs[2][8][132];
    const int bh = blockIdx.z;
    const float* A  = g_QQ + (size_t)bh * NSEQ * 2 * ND;
    const float* Bm = g_KK + (size_t)bh * NSEQ * 2 * ND;
    float* Cp = g_P + (size_t)bh * NSEQ * NSEQ;
    const int K  = 2 * ND;
    const int bm = blockIdx.y * 128;
    const int bn = blockIdx.x * 128;
    const int t  = threadIdx.x;
    const int ty = t >> 4, tx = t & 15;
    const int lr = t >> 1, lc = (t & 1) * 4;   // 128 rows x 8 cols, 4 floats/thr

    const float* aptr = A  + (size_t)(bm + lr) * K + lc;
    const float* bptr = Bm + (size_t)(bn + lr) * K + lc;

    float4 ra = *(const float4*)(aptr);
    float4 rb = *(const float4*)(bptr);
    As[0][lc + 0][lr] = ra.x; As[0][lc + 1][lr] = ra.y;
    As[0][lc + 2][lr] = ra.z; As[0][lc + 3][lr] = ra.w;
    Bs[0][lc + 0][lr] = rb.x; Bs[0][lc + 1][lr] = rb.y;
    Bs[0][lc + 2][lr] = rb.z; Bs[0][lc + 3][lr] = rb.w;
    __syncthreads();

    float acc[8][8] = {};
    const int NIT = K / 8;     // 16
    for (int it = 0; it < NIT; ++it) {
        const int cur = it & 1;
        if (it + 1 < NIT) {
            ra = *(const float4*)(aptr + (it + 1) * 8);
            rb = *(const float4*)(bptr + (it + 1) * 8);
        }
        #pragma unroll
        for (int kk = 0; kk < 8; kk++) {
            float a[8], b[8];
            *(float4*)(a)     = *(const float4*)&As[cur][kk][ty * 8];
            *(float4*)(a + 4) = *(const float4*)&As[cur][kk][ty * 8 + 4];
            *(float4*)(b)     = *(const float4*)&Bs[cur][kk][tx * 8];
            *(float4*)(b + 4) = *(const float4*)&Bs[cur][kk][tx * 8 + 4];
            #pragma unroll
            for (int i = 0; i < 8; i++)
                #pragma unroll
                for (int j = 0; j < 8; j++)
                    acc[i][j] = fmaf(a[i], b[j], acc[i][j]);
        }
        if (it + 1 < NIT) {
            const int nxt = cur ^ 1;
            As[nxt][lc + 0][lr] = ra.x; As[nxt][lc + 1][lr] = ra.y;
            As[nxt][lc + 2][lr] = ra.z; As[nxt][lc + 3][lr] = ra.w;
            Bs[nxt][lc + 0][lr] = rb.x; Bs[nxt][lc + 1][lr] = rb.y;
            Bs[nxt][lc + 2][lr] = rb.z; Bs[nxt][lc + 3][lr] = rb.w;
        }
        __syncthreads();
    }

    #pragma unroll
    for (int i = 0; i < 8; i++) {
        const int r = bm + ty * 8 + i;
        float4 v0, v1;
        v0.x = acc[i][0] * ATT_SCALE; v0.y = acc[i][1] * ATT_SCALE;
        v0.z = acc[i][2] * ATT_SCALE; v0.w = acc[i][3] * ATT_SCALE;
        v1.x = acc[i][4] * ATT_SCALE; v1.y = acc[i][5] * ATT_SCALE;
        v1.z = acc[i][6] * ATT_SCALE; v1.w = acc[i][7] * ATT_SCALE;
        *(float4*)&Cp[(size_t)r * NSEQ + bn + tx * 8]     = v0;
        *(float4*)&Cp[(size_t)r * NSEQ + bn + tx * 8 + 4] = v1;
    }
}

// ============================================================================
// Row softmax over 2048 columns. One 256-thread block per row.
// ============================================================================
__global__ void __launch_bounds__(256) softmax_kernel()
{
    __shared__ float red[8];
    float* p = g_P + (size_t)blockIdx.x * NSEQ;
    const int t = threadIdx.x;

    float v[8];
    float mx = -1e30f;
    #pragma unroll
    for (int i = 0; i < 8; i++) { v[i] = p[t + i * 256]; mx = fmaxf(mx, v[i]); }
    #pragma unroll
    for (int o = 16; o; o >>= 1) mx = fmaxf(mx, __shfl_xor_sync(0xFFFFFFFFu, mx, o));
    if ((t & 31) == 0) red[t >> 5] = mx;
    __syncthreads();
    mx = red[0];
    #pragma unroll
    for (int w = 1; w < 8; w++) mx = fmaxf(mx, red[w]);
    __syncthreads();

    float s = 0.f;
    #pragma unroll
    for (int i = 0; i < 8; i++) { v[i] = __expf(v[i] - mx); s += v[i]; }
    #pragma unroll
    for (int o = 16; o; o >>= 1) s += __shfl_xor_sync(0xFFFFFFFFu, s, o);
    if ((t & 31) == 0) red[t >> 5] = s;
    __syncthreads();
    s = red[0];
    #pragma unroll
    for (int w = 1; w < 8; w++) s += red[w];
    const float inv = 1.f / s;
    #pragma unroll
    for (int i = 0; i < 8; i++) p[t + i * 256] = v[i] * inv;
}

// ============================================================================
// ctx = P @ V per (b,h): M=2048, N=64, K=2048 (NN). Tile 128x64, BK=16, 8x4/thr.
// ============================================================================
__global__ void __launch_bounds__(256, 2) av_kernel()
{
    __shared__ float As[2][16][132];
    __shared__ float Bs[2][16][68];
    const int bh = blockIdx.z;
    const float* A  = g_P + (size_t)bh * NSEQ * NSEQ;
    const float* Vp = g_V + (size_t)bh * NSEQ * ND;
    const int bm = blockIdx.y * 128;
    const int t  = threadIdx.x;
    const int ty = t >> 4, tx = t & 15;
    const int ar = t >> 1, ac = (t & 1) * 8;   // A: 128 x 16
    const int vk = t >> 4, vn = (t & 15) * 4;  // V:  16 x 64

    const float* aptr = A  + (size_t)(bm + ar) * NSEQ + ac;
    const float* vptr = Vp + (size_t)vk * ND + vn;

    float4 ra0 = *(const float4*)(aptr);
    float4 ra1 = *(const float4*)(aptr + 4);
    float4 rv  = *(const float4*)(vptr);
    As[0][ac + 0][ar] = ra0.x; As[0][ac + 1][ar] = ra0.y;
    As[0][ac + 2][ar] = ra0.z; As[0][ac + 3][ar] = ra0.w;
    As[0][ac + 4][ar] = ra1.x; As[0][ac + 5][ar] = ra1.y;
    As[0][ac + 6][ar] = ra1.z; As[0][ac + 7][ar] = ra1.w;
    *(float4*)&Bs[0][vk][vn] = rv;
    __syncthreads();

    float acc[8][4] = {};
    const int NIT = NSEQ / 16;   // 128
    for (int it = 0; it < NIT; ++it) {
        const int cur = it & 1;
        if (it + 1 < NIT) {
            ra0 = *(const float4*)(aptr + (it + 1) * 16);
            ra1 = *(const float4*)(aptr + (it + 1) * 16 + 4);
            rv  = *(const float4*)(vptr + (size_t)(it + 1) * 16 * ND);
        }
        #pragma unroll
        for (int kk = 0; kk < 16; kk++) {
            float a[8], b[4];
            *(float4*)(a)     = *(const float4*)&As[cur][kk][ty * 8];
            *(float4*)(a + 4) = *(const float4*)&As[cur][kk][ty * 8 + 4];
            *(float4*)(b)     = *(const float4*)&Bs[cur][kk][tx * 4];
            #pragma unroll
            for (int i = 0; i < 8; i++)
                #pragma unroll
                for (int j = 0; j < 4; j++)
                    acc[i][j] = fmaf(a[i], b[j], acc[i][j]);
        }
        if (it + 1 < NIT) {
            const int nxt = cur ^ 1;
            As[nxt][ac + 0][ar] = ra0.x; As[nxt][ac + 1][ar] = ra0.y;
            As[nxt][ac + 2][ar] = ra0.z; As[nxt][ac + 3][ar] = ra0.w;
            As[nxt][ac + 4][ar] = ra1.x; As[nxt][ac + 5][ar] = ra1.y;
            As[nxt][ac + 6][ar] = ra1.z; As[nxt][ac + 7][ar] = ra1.w;
            *(float4*)&Bs[nxt][vk][vn] = rv;
        }
        __syncthreads();
    }

    const int b = bh >> 4, h = bh & 15;
    #pragma unroll
    for (int i = 0; i < 8; i++) {
        const int n = bm + ty * 8 + i;
        float4 val;
        val.x = acc[i][0]; val.y = acc[i][1];
        val.z = acc[i][2]; val.w = acc[i][3];
        *(float4*)&g_ctx[((size_t)(b * NSEQ + n)) * NC + h * ND + tx * 4] = val;
    }
}

// ============================================================================
extern "C" void kernel_launch(void* const* d_in, const int* in_sizes, int n_in,
                              void* d_out, int out_size)
{
    const float* hs   = (const float*)d_in[0];
    const float* pe   = (const float*)d_in[1];
    const float* Wq   = (const float*)d_in[2];
    const float* bq   = (const float*)d_in[3];
    const float* Wk   = (const float*)d_in[4];
    const float* bk   = (const float*)d_in[5];
    const float* Wv   = (const float*)d_in[6];
    const float* bv   = (const float*)d_in[7];
    const float* Wpos = (const float*)d_in[8];
    const float* pbu  = (const float*)d_in[9];
    const float* pbv  = (const float*)d_in[10];
    const float* Wo   = (const float*)d_in[11];
    const float* bo   = (const float*)d_in[12];
    float* out = (float*)d_out;

    const dim3 gproj(NC / 64, (NB * NSEQ) / 128);          // (16, 32) = 512 CTAs
    proj_kernel<0><<<gproj, 256>>>(hs, Wq, bq, pbu, pbv, nullptr);
    proj_kernel<1><<<gproj, 256>>>(hs, Wk, bk, nullptr, nullptr, nullptr);
    proj_kernel<2><<<gproj, 256>>>(pe, Wpos, nullptr, nullptr, nullptr, nullptr);
    proj_kernel<3><<<gproj, 256>>>(hs, Wv, bv, nullptr, nullptr, nullptr);

    const dim3 glog(NSEQ / 128, NSEQ / 128, NB * NH);      // (16, 16, 32) = 8192 CTAs
    logits_kernel<<<glog, 256>>>();

    softmax_kernel<<<NB * NH * NSEQ, 256>>>();             // 65536 rows

    const dim3 gav(1, NSEQ / 128, NB * NH);                // (1, 16, 32) = 512 CTAs
    av_kernel<<<gav, 256>>>();

    proj_kernel<4><<<gproj, 256>>>(nullptr, Wo, bo, nullptr, nullptr, out);
}

// round 4
// speedup vs baseline: 1.8574x; 1.5664x over previous
#include <cuda_runtime.h>
#include <cuda_bf16.h>
#include <stdint.h>
#include <math.h>

#define NB   2
#define NSEQ 2048
#define NC   1024
#define NH   16
#define ND   64
#define ATT_SCALE 0.125f

// ---- scratch (device globals) ----
__device__ float g_QQ [(size_t)NB * NH * NSEQ * 2 * ND];   // [q+u | q+v] (B,H,N,128)
__device__ float g_KK [(size_t)NB * NH * NSEQ * 2 * ND];   // [k | p]     (B,H,N,128)
__device__ float g_V  [(size_t)NB * NH * ND * NSEQ];       // TRANSPOSED  (B,H,D,N)
__device__ float g_P  [(size_t)NB * NH * NSEQ * NSEQ];     // logits/probs fp32
__device__ float g_ctx[(size_t)NB * NSEQ * NC];            // (B,N,C)

// XOR-swizzled smem word index: row stride 8 words (16 bf16 of k per row)
__device__ __forceinline__ int SW(int r, int w) { return (r << 3) + (w ^ (r & 7)); }

// fp32 pair -> packed bf16 hi + packed bf16 lo (3-term split)
__device__ __forceinline__ uint32_t pack_split(float x, float y, uint32_t& lo_out) {
    __nv_bfloat162 h = __floats2bfloat162_rn(x, y);
    __nv_bfloat162 l = __floats2bfloat162_rn(x - __bfloat162float(h.x),
                                             y - __bfloat162float(h.y));
    lo_out = *reinterpret_cast<uint32_t*>(&l);
    return *reinterpret_cast<uint32_t*>(&h);
}

__device__ __forceinline__ void stage8(uint32_t* sh, uint32_t* sl,
                                       int row, int w0,
                                       const float4& v0, const float4& v1) {
    uint32_t lo, hi;
    hi = pack_split(v0.x, v0.y, lo); sh[SW(row, w0 + 0)] = hi; sl[SW(row, w0 + 0)] = lo;
    hi = pack_split(v0.z, v0.w, lo); sh[SW(row, w0 + 1)] = hi; sl[SW(row, w0 + 1)] = lo;
    hi = pack_split(v1.x, v1.y, lo); sh[SW(row, w0 + 2)] = hi; sl[SW(row, w0 + 2)] = lo;
    hi = pack_split(v1.z, v1.w, lo); sh[SW(row, w0 + 3)] = hi; sl[SW(row, w0 + 3)] = lo;
}

__device__ __forceinline__ void stage4(uint32_t* sh, uint32_t* sl,
                                       int row, int w0, const float4& v0) {
    uint32_t lo, hi;
    hi = pack_split(v0.x, v0.y, lo); sh[SW(row, w0 + 0)] = hi; sl[SW(row, w0 + 0)] = lo;
    hi = pack_split(v0.z, v0.w, lo); sh[SW(row, w0 + 1)] = hi; sl[SW(row, w0 + 1)] = lo;
}

#define MMA(d, A0, A1, A2, A3, B0, B1)                                   \
    asm volatile("mma.sync.aligned.m16n8k16.row.col.f32.bf16.bf16.f32 "  \
                 "{%0,%1,%2,%3},{%4,%5,%6,%7},{%8,%9},{%0,%1,%2,%3};"    \
                 : "+f"(d[0]), "+f"(d[1]), "+f"(d[2]), "+f"(d[3])        \
                 : "r"(A0), "r"(A1), "r"(A2), "r"(A3), "r"(B0), "r"(B1))

// ============================================================================
// Unified 128x128 tile bf16x3 GEMM. A: row-major MxK, B: row-major NxK (col B).
// MODE 0..4: projections (K=1024). MODE 5: logits (K=128, per-bh from globals).
// ============================================================================
template <int MODE>
__global__ void __launch_bounds__(256, 1) gemm_mma(
    const float* __restrict__ Ain, const float* __restrict__ Win,
    const float* __restrict__ b1, const float* __restrict__ pbu,
    const float* __restrict__ pbv, float* __restrict__ out)
{
    constexpr int K   = (MODE == 5) ? 128 : 1024;
    constexpr int NIT = K / 16;
    __shared__ uint32_t sAh[2][1024], sAl[2][1024], sBh[2][1024], sBl[2][1024];

    const int bm = blockIdx.y * 128, bn = blockIdx.x * 128;
    const int t = threadIdx.x, lane = t & 31, wid = t >> 5;
    const int g = lane >> 2, tg = lane & 3;
    const int wm = wid & 1, wn = wid >> 1;
    const int ra = t >> 1, kh = t & 1;       // loader: row, k-half
    const int w0 = kh * 4;

    const float *Abase, *Bbase;
    if (MODE == 5) {
        const int bh = blockIdx.z;
        Abase = g_QQ + (size_t)bh * NSEQ * 128;
        Bbase = g_KK + (size_t)bh * NSEQ * 128;
    } else {
        Abase = (MODE == 4) ? g_ctx : Ain;
        Bbase = Win;
    }
    const float* aptr = Abase + (size_t)(bm + ra) * K + kh * 8;
    const float* bptr = Bbase + (size_t)(bn + ra) * K + kh * 8;

    float4 av0 = *(const float4*)(aptr);
    float4 av1 = *(const float4*)(aptr + 4);
    float4 bv0 = *(const float4*)(bptr);
    float4 bv1 = *(const float4*)(bptr + 4);
    stage8(sAh[0], sAl[0], ra, w0, av0, av1);
    stage8(sBh[0], sBl[0], ra, w0, bv0, bv1);
    __syncthreads();

    float acc[4][4][4] = {};
    for (int it = 0; it < NIT; ++it) {
        const int cur = it & 1;
        if (it + 1 < NIT) {
            av0 = *(const float4*)(aptr + (it + 1) * 16);
            av1 = *(const float4*)(aptr + (it + 1) * 16 + 4);
            bv0 = *(const float4*)(bptr + (it + 1) * 16);
            bv1 = *(const float4*)(bptr + (it + 1) * 16 + 4);
        }
        uint32_t bhf[4][2], blf[4][2];
        #pragma unroll
        for (int ni = 0; ni < 4; ni++) {
            const int rb = wn * 32 + ni * 8 + g;
            bhf[ni][0] = sBh[cur][SW(rb, tg)];  bhf[ni][1] = sBh[cur][SW(rb, tg + 4)];
            blf[ni][0] = sBl[cur][SW(rb, tg)];  blf[ni][1] = sBl[cur][SW(rb, tg + 4)];
        }
        #pragma unroll
        for (int mi = 0; mi < 4; mi++) {
            const int r0 = wm * 64 + mi * 16 + g;
            uint32_t ah0 = sAh[cur][SW(r0, tg)],     ah1 = sAh[cur][SW(r0 + 8, tg)];
            uint32_t ah2 = sAh[cur][SW(r0, tg + 4)], ah3 = sAh[cur][SW(r0 + 8, tg + 4)];
            uint32_t al0 = sAl[cur][SW(r0, tg)],     al1 = sAl[cur][SW(r0 + 8, tg)];
            uint32_t al2 = sAl[cur][SW(r0, tg + 4)], al3 = sAl[cur][SW(r0 + 8, tg + 4)];
            #pragma unroll
            for (int ni = 0; ni < 4; ni++) {
                MMA(acc[mi][ni], ah0, ah1, ah2, ah3, bhf[ni][0], bhf[ni][1]);
                MMA(acc[mi][ni], ah0, ah1, ah2, ah3, blf[ni][0], blf[ni][1]);
                MMA(acc[mi][ni], al0, al1, al2, al3, bhf[ni][0], bhf[ni][1]);
            }
        }
        if (it + 1 < NIT) {
            const int nxt = cur ^ 1;
            stage8(sAh[nxt], sAl[nxt], ra, w0, av0, av1);
            stage8(sBh[nxt], sBl[nxt], ra, w0, bv0, bv1);
        }
        __syncthreads();
    }

    // ---- epilogue ----
    float* Cp = nullptr;
    if (MODE == 5) Cp = g_P + (size_t)blockIdx.z * NSEQ * NSEQ;
    #pragma unroll
    for (int mi = 0; mi < 4; mi++) {
        #pragma unroll
        for (int half = 0; half < 2; half++) {
            const int row = bm + wm * 64 + mi * 16 + g + half * 8;
            const int b = row >> 11, n = row & (NSEQ - 1);
            #pragma unroll
            for (int ni = 0; ni < 4; ni++) {
                const int col = bn + wn * 32 + ni * 8 + tg * 2;
                float v0 = acc[mi][ni][half * 2 + 0];
                float v1 = acc[mi][ni][half * 2 + 1];
                if (MODE == 5) {
                    *(float2*)&Cp[(size_t)row * NSEQ + col] =
                        make_float2(v0 * ATT_SCALE, v1 * ATT_SCALE);
                    continue;
                }
                const int h = col >> 6, d = col & 63;
                if (MODE != 2) { v0 += b1[col]; v1 += b1[col + 1]; }
                if (MODE == 0) {
                    const size_t base = (((size_t)(b * NH + h)) * NSEQ + n) * 128;
                    *(float2*)&g_QQ[base + d] =
                        make_float2(v0 + pbu[h * 64 + d], v1 + pbu[h * 64 + d + 1]);
                    *(float2*)&g_QQ[base + 64 + d] =
                        make_float2(v0 + pbv[h * 64 + d], v1 + pbv[h * 64 + d + 1]);
                } else if (MODE == 1) {
                    *(float2*)&g_KK[(((size_t)(b * NH + h)) * NSEQ + n) * 128 + d] =
                        make_float2(v0, v1);
                } else if (MODE == 2) {
                    *(float2*)&g_KK[(((size_t)(b * NH + h)) * NSEQ + n) * 128 + 64 + d] =
                        make_float2(v0, v1);
                } else if (MODE == 3) {
                    // transposed V: (B,H,D,N)
                    g_V[(((size_t)(b * NH + h)) * ND + d)     * NSEQ + n] = v0;
                    g_V[(((size_t)(b * NH + h)) * ND + d + 1) * NSEQ + n] = v1;
                } else {
                    *(float2*)&out[(size_t)row * NC + col] = make_float2(v0, v1);
                }
            }
        }
    }
}

// ============================================================================
// Row softmax over 2048 columns (fp32).
// ============================================================================
__global__ void __launch_bounds__(256) softmax_kernel()
{
    __shared__ float red[8];
    float* p = g_P + (size_t)blockIdx.x * NSEQ;
    const int t = threadIdx.x;
    float v[8];
    float mx = -1e30f;
    #pragma unroll
    for (int i = 0; i < 8; i++) { v[i] = p[t + i * 256]; mx = fmaxf(mx, v[i]); }
    #pragma unroll
    for (int o = 16; o; o >>= 1) mx = fmaxf(mx, __shfl_xor_sync(0xFFFFFFFFu, mx, o));
    if ((t & 31) == 0) red[t >> 5] = mx;
    __syncthreads();
    mx = red[0];
    #pragma unroll
    for (int w = 1; w < 8; w++) mx = fmaxf(mx, red[w]);
    __syncthreads();
    float s = 0.f;
    #pragma unroll
    for (int i = 0; i < 8; i++) { v[i] = __expf(v[i] - mx); s += v[i]; }
    #pragma unroll
    for (int o = 16; o; o >>= 1) s += __shfl_xor_sync(0xFFFFFFFFu, s, o);
    if ((t & 31) == 0) red[t >> 5] = s;
    __syncthreads();
    s = red[0];
    #pragma unroll
    for (int w = 1; w < 8; w++) s += red[w];
    const float inv = 1.f / s;
    #pragma unroll
    for (int i = 0; i < 8; i++) p[t + i * 256] = v[i] * inv;
}

// ============================================================================
// ctx = P @ V per (b,h): tile 128(M) x 64(N), K=2048, bf16x3 mma.
// B operand = transposed V (B,H,D,N) row-major in d.
// ============================================================================
__global__ void __launch_bounds__(256, 1) av_mma()
{
    constexpr int NIT = NSEQ / 16;   // 128
    __shared__ uint32_t sAh[2][1024], sAl[2][1024], sBh[2][512], sBl[2][512];

    const int bh = blockIdx.z;
    const int bm = blockIdx.y * 128;
    const int t = threadIdx.x, lane = t & 31, wid = t >> 5;
    const int g = lane >> 2, tg = lane & 3;
    const int wm = wid & 3, wn = wid >> 2;         // 4 x 2 warps -> 32x32 warp tile
    const int ra = t >> 1, kh = t & 1;             // A loader
    const int rb = t >> 2, kq = t & 3;             // B loader: 64 rows x 16k
    const int w0 = kh * 4;

    const float* aptr = g_P + (size_t)bh * NSEQ * NSEQ + (size_t)(bm + ra) * NSEQ + kh * 8;
    const float* vptr = g_V + (size_t)bh * ND * NSEQ + (size_t)rb * NSEQ + kq * 4;

    float4 av0 = *(const float4*)(aptr);
    float4 av1 = *(const float4*)(aptr + 4);
    float4 bv0 = *(const float4*)(vptr);
    stage8(sAh[0], sAl[0], ra, w0, av0, av1);
    stage4(sBh[0], sBl[0], rb, kq * 2, bv0);
    __syncthreads();

    float acc[2][4][4] = {};
    for (int it = 0; it < NIT; ++it) {
        const int cur = it & 1;
        if (it + 1 < NIT) {
            av0 = *(const float4*)(aptr + (it + 1) * 16);
            av1 = *(const float4*)(aptr + (it + 1) * 16 + 4);
            bv0 = *(const float4*)(vptr + (it + 1) * 16);
        }
        uint32_t bhf[4][2], blf[4][2];
        #pragma unroll
        for (int ni = 0; ni < 4; ni++) {
            const int rn = wn * 32 + ni * 8 + g;
            bhf[ni][0] = sBh[cur][SW(rn, tg)];  bhf[ni][1] = sBh[cur][SW(rn, tg + 4)];
            blf[ni][0] = sBl[cur][SW(rn, tg)];  blf[ni][1] = sBl[cur][SW(rn, tg + 4)];
        }
        #pragma unroll
        for (int mi = 0; mi < 2; mi++) {
            const int r0 = wm * 32 + mi * 16 + g;
            uint32_t ah0 = sAh[cur][SW(r0, tg)],     ah1 = sAh[cur][SW(r0 + 8, tg)];
            uint32_t ah2 = sAh[cur][SW(r0, tg + 4)], ah3 = sAh[cur][SW(r0 + 8, tg + 4)];
            uint32_t al0 = sAl[cur][SW(r0, tg)],     al1 = sAl[cur][SW(r0 + 8, tg)];
            uint32_t al2 = sAl[cur][SW(r0, tg + 4)], al3 = sAl[cur][SW(r0 + 8, tg + 4)];
            #pragma unroll
            for (int ni = 0; ni < 4; ni++) {
                MMA(acc[mi][ni], ah0, ah1, ah2, ah3, bhf[ni][0], bhf[ni][1]);
                MMA(acc[mi][ni], ah0, ah1, ah2, ah3, blf[ni][0], blf[ni][1]);
                MMA(acc[mi][ni], al0, al1, al2, al3, bhf[ni][0], bhf[ni][1]);
            }
        }
        if (it + 1 < NIT) {
            const int nxt = cur ^ 1;
            stage8(sAh[nxt], sAl[nxt], ra, w0, av0, av1);
            stage4(sBh[nxt], sBl[nxt], rb, kq * 2, bv0);
        }
        __syncthreads();
    }

    const int b = bh >> 4, h = bh & 15;
    #pragma unroll
    for (int mi = 0; mi < 2; mi++) {
        #pragma unroll
        for (int half = 0; half < 2; half++) {
            const int n = bm + wm * 32 + mi * 16 + g + half * 8;
            #pragma unroll
            for (int ni = 0; ni < 4; ni++) {
                const int cl = wn * 32 + ni * 8 + tg * 2;
                *(float2*)&g_ctx[((size_t)(b * NSEQ + n)) * NC + h * ND + cl] =
                    make_float2(acc[mi][ni][half * 2 + 0], acc[mi][ni][half * 2 + 1]);
            }
        }
    }
}

// ============================================================================
extern "C" void kernel_launch(void* const* d_in, const int* in_sizes, int n_in,
                              void* d_out, int out_size)
{
    const float* hs   = (const float*)d_in[0];
    const float* pe   = (const float*)d_in[1];
    const float* Wq   = (const float*)d_in[2];
    const float* bq   = (const float*)d_in[3];
    const float* Wk   = (const float*)d_in[4];
    const float* bk   = (const float*)d_in[5];
    const float* Wv   = (const float*)d_in[6];
    const float* bv   = (const float*)d_in[7];
    const float* Wpos = (const float*)d_in[8];
    const float* pbu  = (const float*)d_in[9];
    const float* pbv  = (const float*)d_in[10];
    const float* Wo   = (const float*)d_in[11];
    const float* bo   = (const float*)d_in[12];
    float* out = (float*)d_out;

    const dim3 gproj(NC / 128, (NB * NSEQ) / 128, 1);      // (8, 32)
    gemm_mma<0><<<gproj, 256>>>(hs, Wq, bq, pbu, pbv, nullptr);
    gemm_mma<1><<<gproj, 256>>>(hs, Wk, bk, nullptr, nullptr, nullptr);
    gemm_mma<2><<<gproj, 256>>>(pe, Wpos, nullptr, nullptr, nullptr, nullptr);
    gemm_mma<3><<<gproj, 256>>>(hs, Wv, bv, nullptr, nullptr, nullptr);

    const dim3 glog(NSEQ / 128, NSEQ / 128, NB * NH);      // (16, 16, 32)
    gemm_mma<5><<<glog, 256>>>(nullptr, nullptr, nullptr, nullptr, nullptr, nullptr);

    softmax_kernel<<<NB * NH * NSEQ, 256>>>();

    const dim3 gav(1, NSEQ / 128, NB * NH);                // (1, 16, 32)
    av_mma<<<gav, 256>>>();

    gemm_mma<4><<<gproj, 256>>>(nullptr, Wo, bo, nullptr, nullptr, out);
}

// round 5
// speedup vs baseline: 2.5512x; 1.3735x over previous
#include <cuda_runtime.h>
#include <cuda_bf16.h>
#include <stdint.h>

#define NB   2
#define NSEQ 2048
#define NC   1024
#define NH   16
#define ND   64
#define ATT_SCALE 0.125f

// ---- bf16 hi/lo split scratch (device globals) ----
__device__ __nv_bfloat16 g_hsH[(size_t)NB*NSEQ*NC],  g_hsL[(size_t)NB*NSEQ*NC];
__device__ __nv_bfloat16 g_peH[(size_t)NB*NSEQ*NC],  g_peL[(size_t)NB*NSEQ*NC];
__device__ __nv_bfloat16 g_WH[5][(size_t)NC*NC],     g_WL[5][(size_t)NC*NC]; // q,k,pos,v,o
__device__ __nv_bfloat16 g_QQH[(size_t)NB*NH*NSEQ*128], g_QQL[(size_t)NB*NH*NSEQ*128];
__device__ __nv_bfloat16 g_KKH[(size_t)NB*NH*NSEQ*128], g_KKL[(size_t)NB*NH*NSEQ*128];
__device__ __nv_bfloat16 g_VH[(size_t)NB*NH*ND*NSEQ],   g_VL[(size_t)NB*NH*ND*NSEQ]; // (B,H,D,N)
__device__ float         g_P [(size_t)NB*NH*NSEQ*NSEQ];                              // logits fp32
__device__ __nv_bfloat16 g_PH[(size_t)NB*NH*NSEQ*NSEQ], g_PL[(size_t)NB*NH*NSEQ*NSEQ];
__device__ __nv_bfloat16 g_ctxH[(size_t)NB*NSEQ*NC],    g_ctxL[(size_t)NB*NSEQ*NC];

// ---- helpers ----
__device__ __forceinline__ uint32_t pack_split(float x, float y, uint32_t& lo_out) {
    __nv_bfloat162 h = __floats2bfloat162_rn(x, y);
    __nv_bfloat162 l = __floats2bfloat162_rn(x - __bfloat162float(h.x),
                                             y - __bfloat162float(h.y));
    lo_out = *reinterpret_cast<uint32_t*>(&l);
    return *reinterpret_cast<uint32_t*>(&h);
}

__device__ __forceinline__ void cp16(uint32_t dst, const void* src) {
    asm volatile("cp.async.cg.shared.global [%0], [%1], 16;" :: "r"(dst), "l"(src));
}
__device__ __forceinline__ void cp_commit() {
    asm volatile("cp.async.commit_group;" ::: "memory");
}
template<int N> __device__ __forceinline__ void cp_wait() {
    asm volatile("cp.async.wait_group %0;" :: "n"(N) : "memory");
}
__device__ __forceinline__ void ldsm_x4(uint32_t* r, uint32_t a) {
    asm volatile("ldmatrix.sync.aligned.m8n8.x4.shared.b16 {%0,%1,%2,%3}, [%4];"
                 : "=r"(r[0]), "=r"(r[1]), "=r"(r[2]), "=r"(r[3]) : "r"(a));
}
__device__ __forceinline__ void ldsm_x2(uint32_t* r, uint32_t a) {
    asm volatile("ldmatrix.sync.aligned.m8n8.x2.shared.b16 {%0,%1}, [%2];"
                 : "=r"(r[0]), "=r"(r[1]) : "r"(a));
}

#define MMA(d, A0, A1, A2, A3, B0, B1)                                   \
    asm volatile("mma.sync.aligned.m16n8k16.row.col.f32.bf16.bf16.f32 "  \
                 "{%0,%1,%2,%3},{%4,%5,%6,%7},{%8,%9},{%0,%1,%2,%3};"    \
                 : "+f"(d[0]), "+f"(d[1]), "+f"(d[2]), "+f"(d[3])        \
                 : "r"(A0), "r"(A1), "r"(A2), "r"(A3), "r"(B0), "r"(B1))

// swizzled 16B-chunk unit for (row, chunk): conflict-free for ldmatrix + cp.async
__device__ __forceinline__ int UNIT(int r, int c) { return r * 2 + (c ^ ((r >> 2) & 1)); }

// ============================================================================
// Pre-pass: split fp32 tensors into bf16 hi/lo planes.
// T: 0=hs, 1=pe, 2..6 = W[q,k,pos,v,o]
// ============================================================================
template<int T>
__global__ void __launch_bounds__(256) split_kernel(const float4* __restrict__ src, int n4)
{
    const int i = blockIdx.x * 256 + threadIdx.x;
    if (i >= n4) return;
    __nv_bfloat16 *H, *L;
    if constexpr (T == 0)      { H = g_hsH; L = g_hsL; }
    else if constexpr (T == 1) { H = g_peH; L = g_peL; }
    else                       { H = g_WH[T - 2]; L = g_WL[T - 2]; }
    const float4 v = src[i];
    uint32_t l0, l1;
    const uint32_t h0 = pack_split(v.x, v.y, l0);
    const uint32_t h1 = pack_split(v.z, v.w, l1);
    *(uint2*)(H + (size_t)i * 4) = make_uint2(h0, h1);
    *(uint2*)(L + (size_t)i * 4) = make_uint2(l0, l1);
}

// ============================================================================
// Unified 128x128 bf16x3 GEMM: cp.async -> swizzled smem -> ldmatrix -> mma.
// A [M][K], B [N][K] bf16 hi/lo row-major.
// MODE 0..3: projections (K=1024). MODE 4: out-proj. MODE 5: logits (K=128).
// ============================================================================
template <int MODE>
__global__ void __launch_bounds__(256, 2) gemm_bf16(
    const float* __restrict__ b1, const float* __restrict__ pbu,
    const float* __restrict__ pbv, float* __restrict__ out)
{
    constexpr int K   = (MODE == 5) ? 128 : 1024;
    constexpr int NIT = K / 16;
    constexpr int STG = 16384;   // per-stage: Ah 4K | Al 4K | Bh 4K | Bl 4K
    __shared__ __align__(16) unsigned char smem[3 * STG];

    const int t = threadIdx.x, lane = t & 31, wid = t >> 5;
    const int g = lane >> 2, tg = lane & 3;
    const int wm = wid & 1, wn = wid >> 1;
    const int bm = blockIdx.y * 128, bn = blockIdx.x * 128;

    const __nv_bfloat16 *AH, *AL, *BH, *BL;
    if constexpr (MODE == 2)      { AH = g_peH;  AL = g_peL; }
    else if constexpr (MODE == 4) { AH = g_ctxH; AL = g_ctxL; }
    else if constexpr (MODE == 5) {
        const size_t o = (size_t)blockIdx.z * NSEQ * 128;
        AH = g_QQH + o; AL = g_QQL + o;
    } else                        { AH = g_hsH;  AL = g_hsL; }
    if constexpr (MODE == 5) {
        const size_t o = (size_t)blockIdx.z * NSEQ * 128;
        BH = g_KKH + o; BL = g_KKL + o;
    } else                        { BH = g_WH[MODE]; BL = g_WL[MODE]; }

    const int lr = t >> 1, lc = t & 1;
    const __nv_bfloat16* gah = AH + (size_t)(bm + lr) * K + lc * 8;
    const __nv_bfloat16* gal = AL + (size_t)(bm + lr) * K + lc * 8;
    const __nv_bfloat16* gbh = BH + (size_t)(bn + lr) * K + lc * 8;
    const __nv_bfloat16* gbl = BL + (size_t)(bn + lr) * K + lc * 8;
    const uint32_t sb0 = (uint32_t)__cvta_generic_to_shared(smem);
    const uint32_t lun = (uint32_t)(UNIT(lr, lc) << 4);

    #pragma unroll
    for (int s = 0; s < 2; s++) {
        const uint32_t d = sb0 + s * STG + lun;
        cp16(d,         gah + s * 16);
        cp16(d + 4096,  gal + s * 16);
        cp16(d + 8192,  gbh + s * 16);
        cp16(d + 12288, gbl + s * 16);
        cp_commit();
    }

    uint32_t aoff[4], boff[4];
    {
        const int rr = (lane & 7) + ((lane >> 3) & 1) * 8;
        const int cc = lane >> 4;
        #pragma unroll
        for (int mi = 0; mi < 4; mi++) {
            const int r = wm * 64 + mi * 16 + rr;
            aoff[mi] = (uint32_t)(UNIT(r, cc) << 4);
        }
        const int l15 = lane & 15;
        #pragma unroll
        for (int ni = 0; ni < 4; ni++) {
            const int r = wn * 32 + ni * 8 + (l15 & 7);
            boff[ni] = (uint32_t)(UNIT(r, l15 >> 3) << 4);
        }
    }

    float acc[4][4][4] = {};
    for (int it = 0; it < NIT; ++it) {
        cp_wait<1>();
        __syncthreads();
        const int pf = it + 2;
        if (pf < NIT) {
            const uint32_t d = sb0 + (pf % 3) * STG + lun;
            cp16(d,         gah + pf * 16);
            cp16(d + 4096,  gal + pf * 16);
            cp16(d + 8192,  gbh + pf * 16);
            cp16(d + 12288, gbl + pf * 16);
        }
        cp_commit();

        const uint32_t base = sb0 + (it % 3) * STG;
        uint32_t bhf[4][2], blf[4][2];
        #pragma unroll
        for (int ni = 0; ni < 4; ni++) {
            ldsm_x2(bhf[ni], base + 8192  + boff[ni]);
            ldsm_x2(blf[ni], base + 12288 + boff[ni]);
        }
        #pragma unroll
        for (int mi = 0; mi < 4; mi++) {
            uint32_t ah[4], al[4];
            ldsm_x4(ah, base + aoff[mi]);
            ldsm_x4(al, base + 4096 + aoff[mi]);
            #pragma unroll
            for (int ni = 0; ni < 4; ni++) {
                MMA(acc[mi][ni], ah[0], ah[1], ah[2], ah[3], bhf[ni][0], bhf[ni][1]);
                MMA(acc[mi][ni], ah[0], ah[1], ah[2], ah[3], blf[ni][0], blf[ni][1]);
                MMA(acc[mi][ni], al[0], al[1], al[2], al[3], bhf[ni][0], bhf[ni][1]);
            }
        }
    }

    // ---- epilogue ----
    #pragma unroll
    for (int mi = 0; mi < 4; mi++) {
        #pragma unroll
        for (int half = 0; half < 2; half++) {
            const int row = bm + wm * 64 + mi * 16 + g + half * 8;
            const int b = row >> 11, n = row & (NSEQ - 1);
            #pragma unroll
            for (int ni = 0; ni < 4; ni++) {
                const int col = bn + wn * 32 + ni * 8 + tg * 2;
                float v0 = acc[mi][ni][half * 2 + 0];
                float v1 = acc[mi][ni][half * 2 + 1];
                if constexpr (MODE == 5) {
                    float* Cp = g_P + (size_t)blockIdx.z * NSEQ * NSEQ;
                    *(float2*)&Cp[(size_t)row * NSEQ + col] =
                        make_float2(v0 * ATT_SCALE, v1 * ATT_SCALE);
                    continue;
                }
                if constexpr (MODE != 2 && MODE != 5) { v0 += b1[col]; v1 += b1[col + 1]; }
                const int h = col >> 6, d = col & 63;
                if constexpr (MODE == 0) {
                    const size_t base = (((size_t)(b * NH + h)) * NSEQ + n) * 128;
                    uint32_t lo, hi;
                    hi = pack_split(v0 + pbu[h * 64 + d], v1 + pbu[h * 64 + d + 1], lo);
                    *(uint32_t*)&g_QQH[base + d] = hi;
                    *(uint32_t*)&g_QQL[base + d] = lo;
                    hi = pack_split(v0 + pbv[h * 64 + d], v1 + pbv[h * 64 + d + 1], lo);
                    *(uint32_t*)&g_QQH[base + 64 + d] = hi;
                    *(uint32_t*)&g_QQL[base + 64 + d] = lo;
                } else if constexpr (MODE == 1) {
                    const size_t base = (((size_t)(b * NH + h)) * NSEQ + n) * 128;
                    uint32_t lo, hi = pack_split(v0, v1, lo);
                    *(uint32_t*)&g_KKH[base + d] = hi;
                    *(uint32_t*)&g_KKL[base + d] = lo;
                } else if constexpr (MODE == 2) {
                    const size_t base = (((size_t)(b * NH + h)) * NSEQ + n) * 128;
                    uint32_t lo, hi = pack_split(v0, v1, lo);
                    *(uint32_t*)&g_KKH[base + 64 + d] = hi;
                    *(uint32_t*)&g_KKL[base + 64 + d] = lo;
                } else if constexpr (MODE == 3) {
                    // transposed V: (B,H,D,N), scalar split stores
                    const size_t vb = (((size_t)(b * NH + h)) * ND + d) * NSEQ + n;
                    __nv_bfloat16 h0 = __float2bfloat16(v0);
                    __nv_bfloat16 l0 = __float2bfloat16(v0 - __bfloat162float(h0));
                    __nv_bfloat16 h1 = __float2bfloat16(v1);
                    __nv_bfloat16 l1 = __float2bfloat16(v1 - __bfloat162float(h1));
                    g_VH[vb] = h0;        g_VL[vb] = l0;
                    g_VH[vb + NSEQ] = h1; g_VL[vb + NSEQ] = l1;
                } else {
                    *(float2*)&out[(size_t)row * NC + col] = make_float2(v0, v1);
                }
            }
        }
    }
}

// ============================================================================
// Row softmax over 2048 cols: read fp32 logits, write bf16 hi/lo prob planes.
// ============================================================================
__global__ void __launch_bounds__(256) softmax_split()
{
    __shared__ float red[8];
    const size_t rb = (size_t)blockIdx.x * NSEQ;
    const float* p = g_P + rb;
    const int t = threadIdx.x;
    const int c0 = t * 8;

    float4 x0 = *(const float4*)(p + c0);
    float4 x1 = *(const float4*)(p + c0 + 4);
    float v[8] = {x0.x, x0.y, x0.z, x0.w, x1.x, x1.y, x1.z, x1.w};
    float mx = v[0];
    #pragma unroll
    for (int i = 1; i < 8; i++) mx = fmaxf(mx, v[i]);
    #pragma unroll
    for (int o = 16; o; o >>= 1) mx = fmaxf(mx, __shfl_xor_sync(0xFFFFFFFFu, mx, o));
    if ((t & 31) == 0) red[t >> 5] = mx;
    __syncthreads();
    mx = red[0];
    #pragma unroll
    for (int w = 1; w < 8; w++) mx = fmaxf(mx, red[w]);
    __syncthreads();

    float s = 0.f;
    #pragma unroll
    for (int i = 0; i < 8; i++) { v[i] = __expf(v[i] - mx); s += v[i]; }
    #pragma unroll
    for (int o = 16; o; o >>= 1) s += __shfl_xor_sync(0xFFFFFFFFu, s, o);
    if ((t & 31) == 0) red[t >> 5] = s;
    __syncthreads();
    s = red[0];
    #pragma unroll
    for (int w = 1; w < 8; w++) s += red[w];
    const float inv = 1.f / s;

    uint32_t h[4], l[4];
    #pragma unroll
    for (int j = 0; j < 4; j++)
        h[j] = pack_split(v[2 * j] * inv, v[2 * j + 1] * inv, l[j]);
    *(uint4*)&g_PH[rb + c0] = make_uint4(h[0], h[1], h[2], h[3]);
    *(uint4*)&g_PL[rb + c0] = make_uint4(l[0], l[1], l[2], l[3]);
}

// ============================================================================
// ctx = P @ V per (b,h): 128(M) x 64(N), K=2048 bf16x3, same pipeline.
// ============================================================================
__global__ void __launch_bounds__(256, 2) av_bf16()
{
    constexpr int NIT = NSEQ / 16;   // 128
    constexpr int STG = 12288;       // Ah 4K | Al 4K | Bh 2K | Bl 2K
    __shared__ __align__(16) unsigned char smem[3 * STG];

    const int bhz = blockIdx.z;
    const int bm = blockIdx.y * 128;
    const int t = threadIdx.x, lane = t & 31, wid = t >> 5;
    const int g = lane >> 2, tg = lane & 3;
    const int wm = wid & 3, wn = wid >> 2;

    const int lr = t >> 1, lc = t & 1;
    const __nv_bfloat16* aH = g_PH + (size_t)bhz * NSEQ * NSEQ + (size_t)(bm + lr) * NSEQ + lc * 8;
    const __nv_bfloat16* aL = g_PL + (size_t)bhz * NSEQ * NSEQ + (size_t)(bm + lr) * NSEQ + lc * 8;
    const __nv_bfloat16* vH = g_VH + (size_t)bhz * ND * NSEQ + (size_t)lr * NSEQ + lc * 8;
    const __nv_bfloat16* vL = g_VL + (size_t)bhz * ND * NSEQ + (size_t)lr * NSEQ + lc * 8;
    const uint32_t sb0 = (uint32_t)__cvta_generic_to_shared(smem);
    const uint32_t lun = (uint32_t)(UNIT(lr, lc) << 4);

    #pragma unroll
    for (int s = 0; s < 2; s++) {
        const uint32_t d = sb0 + s * STG;
        cp16(d + lun,        aH + s * 16);
        cp16(d + 4096 + lun, aL + s * 16);
        if (t < 128) {
            cp16(d + 8192  + lun, vH + s * 16);
            cp16(d + 10240 + lun, vL + s * 16);
        }
        cp_commit();
    }

    uint32_t aoff[2], boff[4];
    {
        const int rr = (lane & 7) + ((lane >> 3) & 1) * 8;
        const int cc = lane >> 4;
        #pragma unroll
        for (int mi = 0; mi < 2; mi++) {
            const int r = wm * 32 + mi * 16 + rr;
            aoff[mi] = (uint32_t)(UNIT(r, cc) << 4);
        }
        const int l15 = lane & 15;
        #pragma unroll
        for (int ni = 0; ni < 4; ni++) {
            const int r = wn * 32 + ni * 8 + (l15 & 7);
            boff[ni] = (uint32_t)(UNIT(r, l15 >> 3) << 4);
        }
    }

    float acc[2][4][4] = {};
    for (int it = 0; it < NIT; ++it) {
        cp_wait<1>();
        __syncthreads();
        const int pf = it + 2;
        if (pf < NIT) {
            const uint32_t d = sb0 + (pf % 3) * STG;
            cp16(d + lun,        aH + pf * 16);
            cp16(d + 4096 + lun, aL + pf * 16);
            if (t < 128) {
                cp16(d + 8192  + lun, vH + pf * 16);
                cp16(d + 10240 + lun, vL + pf * 16);
            }
        }
        cp_commit();

        const uint32_t base = sb0 + (it % 3) * STG;
        uint32_t bhf[4][2], blf[4][2];
        #pragma unroll
        for (int ni = 0; ni < 4; ni++) {
            ldsm_x2(bhf[ni], base + 8192  + boff[ni]);
            ldsm_x2(blf[ni], base + 10240 + boff[ni]);
        }
        #pragma unroll
        for (int mi = 0; mi < 2; mi++) {
            uint32_t ah[4], al[4];
            ldsm_x4(ah, base + aoff[mi]);
            ldsm_x4(al, base + 4096 + aoff[mi]);
            #pragma unroll
            for (int ni = 0; ni < 4; ni++) {
                MMA(acc[mi][ni], ah[0], ah[1], ah[2], ah[3], bhf[ni][0], bhf[ni][1]);
                MMA(acc[mi][ni], ah[0], ah[1], ah[2], ah[3], blf[ni][0], blf[ni][1]);
                MMA(acc[mi][ni], al[0], al[1], al[2], al[3], bhf[ni][0], bhf[ni][1]);
            }
        }
    }

    const int b = bhz >> 4, h = bhz & 15;
    #pragma unroll
    for (int mi = 0; mi < 2; mi++) {
        #pragma unroll
        for (int half = 0; half < 2; half++) {
            const int n = bm + wm * 32 + mi * 16 + g + half * 8;
            #pragma unroll
            for (int ni = 0; ni < 4; ni++) {
                const int cl = wn * 32 + ni * 8 + tg * 2;
                const size_t idx = ((size_t)(b * NSEQ + n)) * NC + h * ND + cl;
                uint32_t lo, hi = pack_split(acc[mi][ni][half * 2 + 0],
                                             acc[mi][ni][half * 2 + 1], lo);
                *(uint32_t*)&g_ctxH[idx] = hi;
                *(uint32_t*)&g_ctxL[idx] = lo;
            }
        }
    }
}

// ============================================================================
extern "C" void kernel_launch(void* const* d_in, const int* in_sizes, int n_in,
                              void* d_out, int out_size)
{
    const float* hs   = (const float*)d_in[0];
    const float* pe   = (const float*)d_in[1];
    const float* Wq   = (const float*)d_in[2];
    const float* bq   = (const float*)d_in[3];
    const float* Wk   = (const float*)d_in[4];
    const float* bk   = (const float*)d_in[5];
    const float* Wv   = (const float*)d_in[6];
    const float* bv   = (const float*)d_in[7];
    const float* Wpos = (const float*)d_in[8];
    const float* pbu  = (const float*)d_in[9];
    const float* pbv  = (const float*)d_in[10];
    const float* Wo   = (const float*)d_in[11];
    const float* bo   = (const float*)d_in[12];
    float* out = (float*)d_out;

    const int n4_act = NB * NSEQ * NC / 4;   // 1048576
    const int n4_w   = NC * NC / 4;          // 262144
    split_kernel<0><<<n4_act / 256, 256>>>((const float4*)hs,   n4_act);
    split_kernel<1><<<n4_act / 256, 256>>>((const float4*)pe,   n4_act);
    split_kernel<2><<<n4_w   / 256, 256>>>((const float4*)Wq,   n4_w);
    split_kernel<3><<<n4_w   / 256, 256>>>((const float4*)Wk,   n4_w);
    split_kernel<4><<<n4_w   / 256, 256>>>((const float4*)Wpos, n4_w);
    split_kernel<5><<<n4_w   / 256, 256>>>((const float4*)Wv,   n4_w);
    split_kernel<6><<<n4_w   / 256, 256>>>((const float4*)Wo,   n4_w);

    const dim3 gproj(NC / 128, (NB * NSEQ) / 128, 1);      // (8, 32)
    gemm_bf16<0><<<gproj, 256>>>(bq, pbu, pbv, nullptr);
    gemm_bf16<1><<<gproj, 256>>>(bk, nullptr, nullptr, nullptr);
    gemm_bf16<2><<<gproj, 256>>>(nullptr, nullptr, nullptr, nullptr);
    gemm_bf16<3><<<gproj, 256>>>(bv, nullptr, nullptr, nullptr);

    const dim3 glog(NSEQ / 128, NSEQ / 128, NB * NH);      // (16, 16, 32)
    gemm_bf16<5><<<glog, 256>>>(nullptr, nullptr, nullptr, nullptr);

    softmax_split<<<NB * NH * NSEQ, 256>>>();

    const dim3 gav(1, NSEQ / 128, NB * NH);                // (1, 16, 32)
    av_bf16<<<gav, 256>>>();

    gemm_bf16<4><<<gproj, 256>>>(bo, nullptr, nullptr, out);
}

// round 6
// speedup vs baseline: 2.8023x; 1.0985x over previous
#include <cuda_runtime.h>
#include <cuda_bf16.h>
#include <stdint.h>

#define NB   2
#define NSEQ 2048
#define NC   1024
#define NH   16
#define ND   64
#define ATT_SCALE 0.125f

// ---- bf16 hi/lo split scratch (device globals) ----
__device__ __nv_bfloat16 g_hsH[(size_t)NB*NSEQ*NC],  g_hsL[(size_t)NB*NSEQ*NC];
__device__ __nv_bfloat16 g_peH[(size_t)NB*NSEQ*NC],  g_peL[(size_t)NB*NSEQ*NC];
__device__ __nv_bfloat16 g_WH[5][(size_t)NC*NC],     g_WL[5][(size_t)NC*NC]; // q,k,pos,v,o
__device__ __nv_bfloat16 g_QQH[(size_t)NB*NH*NSEQ*128], g_QQL[(size_t)NB*NH*NSEQ*128];
__device__ __nv_bfloat16 g_KKH[(size_t)NB*NH*NSEQ*128], g_KKL[(size_t)NB*NH*NSEQ*128];
__device__ __nv_bfloat16 g_VH[(size_t)NB*NH*ND*NSEQ],   g_VL[(size_t)NB*NH*ND*NSEQ]; // (B,H,D,N)
__device__ __nv_bfloat16 g_ctxH[(size_t)NB*NSEQ*NC],    g_ctxL[(size_t)NB*NSEQ*NC];

// ---- helpers ----
__device__ __forceinline__ uint32_t pack_split(float x, float y, uint32_t& lo_out) {
    __nv_bfloat162 h = __floats2bfloat162_rn(x, y);
    __nv_bfloat162 l = __floats2bfloat162_rn(x - __bfloat162float(h.x),
                                             y - __bfloat162float(h.y));
    lo_out = *reinterpret_cast<uint32_t*>(&l);
    return *reinterpret_cast<uint32_t*>(&h);
}

__device__ __forceinline__ void cp16(uint32_t dst, const void* src) {
    asm volatile("cp.async.cg.shared.global [%0], [%1], 16;" :: "r"(dst), "l"(src));
}
__device__ __forceinline__ void cp_commit() {
    asm volatile("cp.async.commit_group;" ::: "memory");
}
template<int N> __device__ __forceinline__ void cp_wait() {
    asm volatile("cp.async.wait_group %0;" :: "n"(N) : "memory");
}
__device__ __forceinline__ void ldsm_x4(uint32_t* r, uint32_t a) {
    asm volatile("ldmatrix.sync.aligned.m8n8.x4.shared.b16 {%0,%1,%2,%3}, [%4];"
                 : "=r"(r[0]), "=r"(r[1]), "=r"(r[2]), "=r"(r[3]) : "r"(a));
}
__device__ __forceinline__ void ldsm_x2(uint32_t* r, uint32_t a) {
    asm volatile("ldmatrix.sync.aligned.m8n8.x2.shared.b16 {%0,%1}, [%2];"
                 : "=r"(r[0]), "=r"(r[1]) : "r"(a));
}

#define MMA(d, A0, A1, A2, A3, B0, B1)                                   \
    asm volatile("mma.sync.aligned.m16n8k16.row.col.f32.bf16.bf16.f32 "  \
                 "{%0,%1,%2,%3},{%4,%5,%6,%7},{%8,%9},{%0,%1,%2,%3};"    \
                 : "+f"(d[0]), "+f"(d[1]), "+f"(d[2]), "+f"(d[3])        \
                 : "r"(A0), "r"(A1), "r"(A2), "r"(A3), "r"(B0), "r"(B1))

// 32B-row tiles (K=16 bf16 stage rows) used by gemm_bf16
__device__ __forceinline__ int UNIT(int r, int c) { return r * 2 + (c ^ ((r >> 2) & 1)); }
// 256B-row tiles (128 bf16/row, 16 chunks of 16B) used by flash
__device__ __forceinline__ int SWZ(int r, int c) { return r * 16 + (c ^ (r & 7)); }

// ============================================================================
// Pre-pass: split fp32 tensors into bf16 hi/lo planes.
// ============================================================================
template<int T>
__global__ void __launch_bounds__(256) split_kernel(const float4* __restrict__ src, int n4)
{
    const int i = blockIdx.x * 256 + threadIdx.x;
    if (i >= n4) return;
    __nv_bfloat16 *H, *L;
    if constexpr (T == 0)      { H = g_hsH; L = g_hsL; }
    else if constexpr (T == 1) { H = g_peH; L = g_peL; }
    else                       { H = g_WH[T - 2]; L = g_WL[T - 2]; }
    const float4 v = src[i];
    uint32_t l0, l1;
    const uint32_t h0 = pack_split(v.x, v.y, l0);
    const uint32_t h1 = pack_split(v.z, v.w, l1);
    *(uint2*)(H + (size_t)i * 4) = make_uint2(h0, h1);
    *(uint2*)(L + (size_t)i * 4) = make_uint2(l0, l1);
}

// ============================================================================
// 128x128 bf16x3 GEMM for projections (K=1024).
// MODE 0..3: q,k,pos,v. MODE 4: out-proj from ctx.
// ============================================================================
template <int MODE>
__global__ void __launch_bounds__(256, 2) gemm_bf16(
    const float* __restrict__ b1, const float* __restrict__ pbu,
    const float* __restrict__ pbv, float* __restrict__ out)
{
    constexpr int K   = 1024;
    constexpr int NIT = K / 16;
    constexpr int STG = 16384;   // Ah 4K | Al 4K | Bh 4K | Bl 4K
    __shared__ __align__(16) unsigned char smem[3 * STG];

    const int t = threadIdx.x, lane = t & 31, wid = t >> 5;
    const int g = lane >> 2, tg = lane & 3;
    const int wm = wid & 1, wn = wid >> 1;
    const int bm = blockIdx.y * 128, bn = blockIdx.x * 128;

    const __nv_bfloat16 *AH, *AL, *BH, *BL;
    if constexpr (MODE == 2)      { AH = g_peH;  AL = g_peL; }
    else if constexpr (MODE == 4) { AH = g_ctxH; AL = g_ctxL; }
    else                          { AH = g_hsH;  AL = g_hsL; }
    BH = g_WH[MODE]; BL = g_WL[MODE];

    const int lr = t >> 1, lc = t & 1;
    const __nv_bfloat16* gah = AH + (size_t)(bm + lr) * K + lc * 8;
    const __nv_bfloat16* gal = AL + (size_t)(bm + lr) * K + lc * 8;
    const __nv_bfloat16* gbh = BH + (size_t)(bn + lr) * K + lc * 8;
    const __nv_bfloat16* gbl = BL + (size_t)(bn + lr) * K + lc * 8;
    const uint32_t sb0 = (uint32_t)__cvta_generic_to_shared(smem);
    const uint32_t lun = (uint32_t)(UNIT(lr, lc) << 4);

    #pragma unroll
    for (int s = 0; s < 2; s++) {
        const uint32_t d = sb0 + s * STG + lun;
        cp16(d,         gah + s * 16);
        cp16(d + 4096,  gal + s * 16);
        cp16(d + 8192,  gbh + s * 16);
        cp16(d + 12288, gbl + s * 16);
        cp_commit();
    }

    uint32_t aoff[4], boff[4];
    {
        const int rr = (lane & 7) + ((lane >> 3) & 1) * 8;
        const int cc = lane >> 4;
        #pragma unroll
        for (int mi = 0; mi < 4; mi++)
            aoff[mi] = (uint32_t)(UNIT(wm * 64 + mi * 16 + rr, cc) << 4);
        const int l15 = lane & 15;
        #pragma unroll
        for (int ni = 0; ni < 4; ni++)
            boff[ni] = (uint32_t)(UNIT(wn * 32 + ni * 8 + (l15 & 7), l15 >> 3) << 4);
    }

    float acc[4][4][4] = {};
    for (int it = 0; it < NIT; ++it) {
        cp_wait<1>();
        __syncthreads();
        const int pf = it + 2;
        if (pf < NIT) {
            const uint32_t d = sb0 + (pf % 3) * STG + lun;
            cp16(d,         gah + pf * 16);
            cp16(d + 4096,  gal + pf * 16);
            cp16(d + 8192,  gbh + pf * 16);
            cp16(d + 12288, gbl + pf * 16);
        }
        cp_commit();

        const uint32_t base = sb0 + (it % 3) * STG;
        uint32_t bhf[4][2], blf[4][2];
        #pragma unroll
        for (int ni = 0; ni < 4; ni++) {
            ldsm_x2(bhf[ni], base + 8192  + boff[ni]);
            ldsm_x2(blf[ni], base + 12288 + boff[ni]);
        }
        #pragma unroll
        for (int mi = 0; mi < 4; mi++) {
            uint32_t ah[4], al[4];
            ldsm_x4(ah, base + aoff[mi]);
            ldsm_x4(al, base + 4096 + aoff[mi]);
            #pragma unroll
            for (int ni = 0; ni < 4; ni++) {
                MMA(acc[mi][ni], ah[0], ah[1], ah[2], ah[3], bhf[ni][0], bhf[ni][1]);
                MMA(acc[mi][ni], ah[0], ah[1], ah[2], ah[3], blf[ni][0], blf[ni][1]);
                MMA(acc[mi][ni], al[0], al[1], al[2], al[3], bhf[ni][0], bhf[ni][1]);
            }
        }
    }

    // ---- epilogue ----
    #pragma unroll
    for (int mi = 0; mi < 4; mi++) {
        #pragma unroll
        for (int half = 0; half < 2; half++) {
            const int row = bm + wm * 64 + mi * 16 + g + half * 8;
            const int b = row >> 11, n = row & (NSEQ - 1);
            #pragma unroll
            for (int ni = 0; ni < 4; ni++) {
                const int col = bn + wn * 32 + ni * 8 + tg * 2;
                float v0 = acc[mi][ni][half * 2 + 0];
                float v1 = acc[mi][ni][half * 2 + 1];
                if constexpr (MODE != 2) { v0 += b1[col]; v1 += b1[col + 1]; }
                const int h = col >> 6, d = col & 63;
                if constexpr (MODE == 0) {
                    const size_t base = (((size_t)(b * NH + h)) * NSEQ + n) * 128;
                    uint32_t lo, hi;
                    hi = pack_split(v0 + pbu[h * 64 + d], v1 + pbu[h * 64 + d + 1], lo);
                    *(uint32_t*)&g_QQH[base + d] = hi;
                    *(uint32_t*)&g_QQL[base + d] = lo;
                    hi = pack_split(v0 + pbv[h * 64 + d], v1 + pbv[h * 64 + d + 1], lo);
                    *(uint32_t*)&g_QQH[base + 64 + d] = hi;
                    *(uint32_t*)&g_QQL[base + 64 + d] = lo;
                } else if constexpr (MODE == 1) {
                    const size_t base = (((size_t)(b * NH + h)) * NSEQ + n) * 128;
                    uint32_t lo, hi = pack_split(v0, v1, lo);
                    *(uint32_t*)&g_KKH[base + d] = hi;
                    *(uint32_t*)&g_KKL[base + d] = lo;
                } else if constexpr (MODE == 2) {
                    const size_t base = (((size_t)(b * NH + h)) * NSEQ + n) * 128;
                    uint32_t lo, hi = pack_split(v0, v1, lo);
                    *(uint32_t*)&g_KKH[base + 64 + d] = hi;
                    *(uint32_t*)&g_KKL[base + 64 + d] = lo;
                } else if constexpr (MODE == 3) {
                    const size_t vb = (((size_t)(b * NH + h)) * ND + d) * NSEQ + n;
                    __nv_bfloat16 h0 = __float2bfloat16(v0);
                    __nv_bfloat16 l0 = __float2bfloat16(v0 - __bfloat162float(h0));
                    __nv_bfloat16 h1 = __float2bfloat16(v1);
                    __nv_bfloat16 l1 = __float2bfloat16(v1 - __bfloat162float(h1));
                    g_VH[vb] = h0;        g_VL[vb] = l0;
                    g_VH[vb + NSEQ] = h1; g_VL[vb + NSEQ] = l1;
                } else {
                    *(float2*)&out[(size_t)row * NC + col] = make_float2(v0, v1);
                }
            }
        }
    }
}

// ============================================================================
// Fused flash attention per (b,h): S = QQ@KK^T*scale, online softmax, O = P@V.
// Q tile resident; stream 16 KV tiles; P stays in registers (C-frag == A-frag).
// ============================================================================
__device__ __forceinline__ void load_tile128(uint32_t sh, uint32_t sl,
    const __nv_bfloat16* gh, const __nv_bfloat16* gl, int qr, int qc0)
{
    #pragma unroll
    for (int c = 0; c < 8; c++) {
        const int ch = qc0 + c;
        cp16(sh + (uint32_t)(SWZ(qr, ch) << 4), gh + (size_t)qr * 128 + ch * 8);
        cp16(sl + (uint32_t)(SWZ(qr, ch) << 4), gl + (size_t)qr * 128 + ch * 8);
    }
    cp_commit();
}
__device__ __forceinline__ void load_tileV(uint32_t sh, uint32_t sl,
    const __nv_bfloat16* gh, const __nv_bfloat16* gl, int vr, int vc0)
{
    #pragma unroll
    for (int c = 0; c < 4; c++) {
        const int ch = vc0 + c;
        cp16(sh + (uint32_t)(SWZ(vr, ch) << 4), gh + (size_t)vr * NSEQ + ch * 8);
        cp16(sl + (uint32_t)(SWZ(vr, ch) << 4), gl + (size_t)vr * NSEQ + ch * 8);
    }
    cp_commit();
}

__global__ void __launch_bounds__(256, 1) flash_kernel()
{
    extern __shared__ __align__(16) unsigned char sm[];
    const uint32_t sb  = (uint32_t)__cvta_generic_to_shared(sm);
    const uint32_t uQh = sb, uQl = sb + 32768;
    const uint32_t uKh = sb + 65536,  uKl = sb + 98304;
    const uint32_t uVh = sb + 131072, uVl = sb + 147456;

    const int bh = blockIdx.y;
    const int bm = blockIdx.x * 128;
    const int t = threadIdx.x, lane = t & 31, wid = t >> 5;
    const int g = lane >> 2, tg = lane & 3;

    const __nv_bfloat16* QH = g_QQH + (size_t)bh * NSEQ * 128 + (size_t)bm * 128;
    const __nv_bfloat16* QL = g_QQL + (size_t)bh * NSEQ * 128 + (size_t)bm * 128;
    const __nv_bfloat16* KH = g_KKH + (size_t)bh * NSEQ * 128;
    const __nv_bfloat16* KL = g_KKL + (size_t)bh * NSEQ * 128;
    const __nv_bfloat16* VH = g_VH  + (size_t)bh * ND * NSEQ;
    const __nv_bfloat16* VL = g_VL  + (size_t)bh * ND * NSEQ;

    const int qr = t >> 1, qc0 = (t & 1) * 8;   // Q/K loader: row, 8 chunks
    const int vr = t >> 2, vc0 = (t & 3) * 4;   // V loader: row, 4 chunks

    load_tile128(uQh, uQl, QH, QL, qr, qc0);                        // group: Q
    load_tile128(uKh, uKl, KH, KL, qr, qc0);                        // group: K0
    load_tileV  (uVh, uVl, VH, VL, vr, vc0);                        // group: V0

    // fragment lane mappings (validated in R5)
    const int rr  = (lane & 7) + ((lane >> 3) & 1) * 8;  // A-frag row
    const int cc  = lane >> 4;                            // A-frag chunk bit
    const int l15 = lane & 15;
    const int brow = (l15 & 7) + (lane >> 4) * 8;         // B-frag x4 row-within-16
    const int bch  = l15 >> 3;                            // B-frag chunk bit

    float m_r[2] = {-1e30f, -1e30f}, l_r[2] = {0.f, 0.f};
    float o_acc[8][4] = {};

    for (int kt = 0; kt < 16; kt++) {
        cp_wait<1>();          // K[kt] (and Q on kt=0) complete; V[kt] may pend
        __syncthreads();

        // ---- S = Q @ K^T (bf16x3) ----
        float acc[16][4] = {};
        #pragma unroll
        for (int kb = 0; kb < 8; kb++) {
            uint32_t ah[4], al[4];
            ldsm_x4(ah, uQh + (uint32_t)(SWZ(wid * 16 + rr, kb * 2 + cc) << 4));
            ldsm_x4(al, uQl + (uint32_t)(SWZ(wid * 16 + rr, kb * 2 + cc) << 4));
            #pragma unroll
            for (int np = 0; np < 8; np++) {
                uint32_t kh4[4], kl4[4];
                ldsm_x4(kh4, uKh + (uint32_t)(SWZ(np * 16 + brow, kb * 2 + bch) << 4));
                ldsm_x4(kl4, uKl + (uint32_t)(SWZ(np * 16 + brow, kb * 2 + bch) << 4));
                MMA(acc[np * 2],     ah[0], ah[1], ah[2], ah[3], kh4[0], kh4[1]);
                MMA(acc[np * 2],     ah[0], ah[1], ah[2], ah[3], kl4[0], kl4[1]);
                MMA(acc[np * 2],     al[0], al[1], al[2], al[3], kh4[0], kh4[1]);
                MMA(acc[np * 2 + 1], ah[0], ah[1], ah[2], ah[3], kh4[2], kh4[3]);
                MMA(acc[np * 2 + 1], ah[0], ah[1], ah[2], ah[3], kl4[2], kl4[3]);
                MMA(acc[np * 2 + 1], al[0], al[1], al[2], al[3], kh4[2], kh4[3]);
            }
        }
        __syncthreads();       // all warps done reading sK
        if (kt < 15)
            load_tile128(uKh, uKl, KH + (size_t)(kt + 1) * 128 * 128,
                                   KL + (size_t)(kt + 1) * 128 * 128, qr, qc0);

        // ---- online softmax (registers only) ----
        float mx0 = -1e30f, mx1 = -1e30f;
        #pragma unroll
        for (int ni = 0; ni < 16; ni++) {
            mx0 = fmaxf(mx0, fmaxf(acc[ni][0], acc[ni][1]));
            mx1 = fmaxf(mx1, fmaxf(acc[ni][2], acc[ni][3]));
        }
        mx0 *= ATT_SCALE; mx1 *= ATT_SCALE;
        mx0 = fmaxf(mx0, __shfl_xor_sync(0xFFFFFFFFu, mx0, 1));
        mx0 = fmaxf(mx0, __shfl_xor_sync(0xFFFFFFFFu, mx0, 2));
        mx1 = fmaxf(mx1, __shfl_xor_sync(0xFFFFFFFFu, mx1, 1));
        mx1 = fmaxf(mx1, __shfl_xor_sync(0xFFFFFFFFu, mx1, 2));
        const float mn0 = fmaxf(m_r[0], mx0), mn1 = fmaxf(m_r[1], mx1);
        const float c0 = __expf(m_r[0] - mn0), c1 = __expf(m_r[1] - mn1);
        m_r[0] = mn0; m_r[1] = mn1;
        float s0 = 0.f, s1 = 0.f;
        #pragma unroll
        for (int ni = 0; ni < 16; ni++) {
            acc[ni][0] = __expf(fmaf(acc[ni][0], ATT_SCALE, -mn0)); s0 += acc[ni][0];
            acc[ni][1] = __expf(fmaf(acc[ni][1], ATT_SCALE, -mn0)); s0 += acc[ni][1];
            acc[ni][2] = __expf(fmaf(acc[ni][2], ATT_SCALE, -mn1)); s1 += acc[ni][2];
            acc[ni][3] = __expf(fmaf(acc[ni][3], ATT_SCALE, -mn1)); s1 += acc[ni][3];
        }
        s0 += __shfl_xor_sync(0xFFFFFFFFu, s0, 1);
        s0 += __shfl_xor_sync(0xFFFFFFFFu, s0, 2);
        s1 += __shfl_xor_sync(0xFFFFFFFFu, s1, 1);
        s1 += __shfl_xor_sync(0xFFFFFFFFu, s1, 2);
        l_r[0] = l_r[0] * c0 + s0;
        l_r[1] = l_r[1] * c1 + s1;
        #pragma unroll
        for (int nj = 0; nj < 8; nj++) {
            o_acc[nj][0] *= c0; o_acc[nj][1] *= c0;
            o_acc[nj][2] *= c1; o_acc[nj][3] *= c1;
        }

        if (kt == 15) cp_wait<0>(); else cp_wait<1>();   // V[kt] complete
        __syncthreads();

        // ---- O += P @ V (P from registers; bf16x3) ----
        #pragma unroll
        for (int kb = 0; kb < 8; kb++) {
            uint32_t ph[4], pl[4];
            ph[0] = pack_split(acc[2 * kb][0],     acc[2 * kb][1],     pl[0]);
            ph[1] = pack_split(acc[2 * kb][2],     acc[2 * kb][3],     pl[1]);
            ph[2] = pack_split(acc[2 * kb + 1][0], acc[2 * kb + 1][1], pl[2]);
            ph[3] = pack_split(acc[2 * kb + 1][2], acc[2 * kb + 1][3], pl[3]);
            #pragma unroll
            for (int np = 0; np < 4; np++) {
                uint32_t vh4[4], vl4[4];
                ldsm_x4(vh4, uVh + (uint32_t)(SWZ(np * 16 + brow, kb * 2 + bch) << 4));
                ldsm_x4(vl4, uVl + (uint32_t)(SWZ(np * 16 + brow, kb * 2 + bch) << 4));
                MMA(o_acc[np * 2],     ph[0], ph[1], ph[2], ph[3], vh4[0], vh4[1]);
                MMA(o_acc[np * 2],     pl[0], pl[1], pl[2], pl[3], vh4[0], vh4[1]);
                MMA(o_acc[np * 2],     ph[0], ph[1], ph[2], ph[3], vl4[0], vl4[1]);
                MMA(o_acc[np * 2 + 1], ph[0], ph[1], ph[2], ph[3], vh4[2], vh4[3]);
                MMA(o_acc[np * 2 + 1], pl[0], pl[1], pl[2], pl[3], vh4[2], vh4[3]);
                MMA(o_acc[np * 2 + 1], ph[0], ph[1], ph[2], ph[3], vl4[2], vl4[3]);
            }
        }
        __syncthreads();       // all warps done reading sV
        if (kt < 15)
            load_tileV(uVh, uVl, VH + (size_t)(kt + 1) * 128,
                                 VL + (size_t)(kt + 1) * 128, vr, vc0);
    }

    // ---- epilogue: normalize, split, store ctx ----
    const int b = bh >> 4, h = bh & 15;
    const float inv0 = 1.f / l_r[0], inv1 = 1.f / l_r[1];
    const int row0 = bm + wid * 16 + g;
    #pragma unroll
    for (int nj = 0; nj < 8; nj++) {
        const int d = h * 64 + nj * 8 + tg * 2;
        uint32_t lo, hi;
        const size_t i0 = ((size_t)(b * NSEQ + row0)) * NC + d;
        hi = pack_split(o_acc[nj][0] * inv0, o_acc[nj][1] * inv0, lo);
        *(uint32_t*)&g_ctxH[i0] = hi; *(uint32_t*)&g_ctxL[i0] = lo;
        const size_t i1 = ((size_t)(b * NSEQ + row0 + 8)) * NC + d;
        hi = pack_split(o_acc[nj][2] * inv1, o_acc[nj][3] * inv1, lo);
        *(uint32_t*)&g_ctxH[i1] = hi; *(uint32_t*)&g_ctxL[i1] = lo;
    }
}

// ============================================================================
extern "C" void kernel_launch(void* const* d_in, const int* in_sizes, int n_in,
                              void* d_out, int out_size)
{
    const float* hs   = (const float*)d_in[0];
    const float* pe   = (const float*)d_in[1];
    const float* Wq   = (const float*)d_in[2];
    const float* bq   = (const float*)d_in[3];
    const float* Wk   = (const float*)d_in[4];
    const float* bk   = (const float*)d_in[5];
    const float* Wv   = (const float*)d_in[6];
    const float* bv   = (const float*)d_in[7];
    const float* Wpos = (const float*)d_in[8];
    const float* pbu  = (const float*)d_in[9];
    const float* pbv  = (const float*)d_in[10];
    const float* Wo   = (const float*)d_in[11];
    const float* bo   = (const float*)d_in[12];
    float* out = (float*)d_out;

    static int smem_set = 0;
    if (!smem_set) {
        cudaFuncSetAttribute(flash_kernel,
                             cudaFuncAttributeMaxDynamicSharedMemorySize, 163840);
        smem_set = 1;
    }

    const int n4_act = NB * NSEQ * NC / 4;
    const int n4_w   = NC * NC / 4;
    split_kernel<0><<<n4_act / 256, 256>>>((const float4*)hs,   n4_act);
    split_kernel<1><<<n4_act / 256, 256>>>((const float4*)pe,   n4_act);
    split_kernel<2><<<n4_w   / 256, 256>>>((const float4*)Wq,   n4_w);
    split_kernel<3><<<n4_w   / 256, 256>>>((const float4*)Wk,   n4_w);
    split_kernel<4><<<n4_w   / 256, 256>>>((const float4*)Wpos, n4_w);
    split_kernel<5><<<n4_w   / 256, 256>>>((const float4*)Wv,   n4_w);
    split_kernel<6><<<n4_w   / 256, 256>>>((const float4*)Wo,   n4_w);

    const dim3 gproj(NC / 128, (NB * NSEQ) / 128, 1);      // (8, 32)
    gemm_bf16<0><<<gproj, 256>>>(bq, pbu, pbv, nullptr);
    gemm_bf16<1><<<gproj, 256>>>(bk, nullptr, nullptr, nullptr);
    gemm_bf16<2><<<gproj, 256>>>(nullptr, nullptr, nullptr, nullptr);
    gemm_bf16<3><<<gproj, 256>>>(bv, nullptr, nullptr, nullptr);

    flash_kernel<<<dim3(NSEQ / 128, NB * NH), 256, 163840>>>();   // (16, 32)

    gemm_bf16<4><<<gproj, 256>>>(bo, nullptr, nullptr, out);
}

// round 7
// speedup vs baseline: 3.0889x; 1.1023x over previous
#include <cuda_runtime.h>
#include <cuda_bf16.h>
#include <stdint.h>

#define NB   2
#define NSEQ 2048
#define NC   1024
#define NH   16
#define ND   64
#define ATT_SCALE 0.125f

// ---- bf16 hi/lo split scratch (device globals) ----
__device__ __nv_bfloat16 g_hsH[(size_t)NB*NSEQ*NC],  g_hsL[(size_t)NB*NSEQ*NC];
__device__ __nv_bfloat16 g_peH[(size_t)NB*NSEQ*NC],  g_peL[(size_t)NB*NSEQ*NC];
__device__ __nv_bfloat16 g_WH[5][(size_t)NC*NC],     g_WL[5][(size_t)NC*NC]; // q,k,pos,v,o
__device__ __nv_bfloat16 g_QQH[(size_t)NB*NH*NSEQ*128], g_QQL[(size_t)NB*NH*NSEQ*128];
__device__ __nv_bfloat16 g_KKH[(size_t)NB*NH*NSEQ*128], g_KKL[(size_t)NB*NH*NSEQ*128];
__device__ __nv_bfloat16 g_VH[(size_t)NB*NH*ND*NSEQ],   g_VL[(size_t)NB*NH*ND*NSEQ]; // (B,H,D,N)
__device__ __nv_bfloat16 g_ctxH[(size_t)NB*NSEQ*NC],    g_ctxL[(size_t)NB*NSEQ*NC];

// ---- helpers ----
__device__ __forceinline__ uint32_t pack_split(float x, float y, uint32_t& lo_out) {
    __nv_bfloat162 h = __floats2bfloat162_rn(x, y);
    __nv_bfloat162 l = __floats2bfloat162_rn(x - __bfloat162float(h.x),
                                             y - __bfloat162float(h.y));
    lo_out = *reinterpret_cast<uint32_t*>(&l);
    return *reinterpret_cast<uint32_t*>(&h);
}
__device__ __forceinline__ void cp16(uint32_t dst, const void* src) {
    asm volatile("cp.async.cg.shared.global [%0], [%1], 16;" :: "r"(dst), "l"(src));
}
__device__ __forceinline__ void cp_commit() {
    asm volatile("cp.async.commit_group;" ::: "memory");
}
template<int N> __device__ __forceinline__ void cp_wait() {
    asm volatile("cp.async.wait_group %0;" :: "n"(N) : "memory");
}
__device__ __forceinline__ void ldsm_x4(uint32_t* r, uint32_t a) {
    asm volatile("ldmatrix.sync.aligned.m8n8.x4.shared.b16 {%0,%1,%2,%3}, [%4];"
                 : "=r"(r[0]), "=r"(r[1]), "=r"(r[2]), "=r"(r[3]) : "r"(a));
}
__device__ __forceinline__ void ldsm_x2(uint32_t* r, uint32_t a) {
    asm volatile("ldmatrix.sync.aligned.m8n8.x2.shared.b16 {%0,%1}, [%2];"
                 : "=r"(r[0]), "=r"(r[1]) : "r"(a));
}

#define MMA(d, A0, A1, A2, A3, B0, B1)                                   \
    asm volatile("mma.sync.aligned.m16n8k16.row.col.f32.bf16.bf16.f32 "  \
                 "{%0,%1,%2,%3},{%4,%5,%6,%7},{%8,%9},{%0,%1,%2,%3};"    \
                 : "+f"(d[0]), "+f"(d[1]), "+f"(d[2]), "+f"(d[3])        \
                 : "r"(A0), "r"(A1), "r"(A2), "r"(A3), "r"(B0), "r"(B1))

__device__ __forceinline__ int UNIT(int r, int c) { return r * 2 + (c ^ ((r >> 2) & 1)); }
__device__ __forceinline__ int SWZ(int r, int c) { return r * 16 + (c ^ (r & 7)); }

// ============================================================================
// Merged pre-pass: split ALL fp32 inputs into bf16 hi/lo planes (one launch).
// ============================================================================
__global__ void __launch_bounds__(256) split_all(
    const float4* __restrict__ hs, const float4* __restrict__ pe,
    const float4* __restrict__ wq, const float4* __restrict__ wk,
    const float4* __restrict__ wpos, const float4* __restrict__ wv,
    const float4* __restrict__ wo)
{
    const int i = blockIdx.x * 256 + threadIdx.x;
    constexpr int A = NB * NSEQ * NC / 4;   // 1048576
    constexpr int W = NC * NC / 4;          // 262144
    const float4* src;
    __nv_bfloat16 *H, *L;
    int off;
    if (i < A)            { src = hs; off = i;     H = g_hsH; L = g_hsL; }
    else if (i < 2 * A)   { src = pe; off = i - A; H = g_peH; L = g_peL; }
    else {
        const int j = i - 2 * A;
        const int w = j >> 18;
        off = j & (W - 1);
        switch (w) {
            case 0:  src = wq;   break;
            case 1:  src = wk;   break;
            case 2:  src = wpos; break;
            case 3:  src = wv;   break;
            default: src = wo;   break;
        }
        H = g_WH[w]; L = g_WL[w];
    }
    const float4 v = src[off];
    uint32_t l0, l1;
    const uint32_t h0 = pack_split(v.x, v.y, l0);
    const uint32_t h1 = pack_split(v.z, v.w, l1);
    *(uint2*)(H + (size_t)off * 4) = make_uint2(h0, h1);
    *(uint2*)(L + (size_t)off * 4) = make_uint2(l0, l1);
}

// ============================================================================
// Merged q/k/pos/v projection GEMM (K=1024): mode = blockIdx.z.
// 128x128 bf16x3 with cp.async + ldmatrix pipeline.
// ============================================================================
__global__ void __launch_bounds__(256, 2) gemm_qkvp(
    const float* __restrict__ bq, const float* __restrict__ bk,
    const float* __restrict__ bv, const float* __restrict__ pbu,
    const float* __restrict__ pbv)
{
    constexpr int K   = 1024;
    constexpr int NIT = K / 16;
    constexpr int STG = 16384;
    __shared__ __align__(16) unsigned char smem[3 * STG];

    const int mode = blockIdx.z;           // 0 q, 1 k, 2 pos, 3 v
    const int t = threadIdx.x, lane = t & 31, wid = t >> 5;
    const int g = lane >> 2, tg = lane & 3;
    const int wm = wid & 1, wn = wid >> 1;
    const int bm = blockIdx.y * 128, bn = blockIdx.x * 128;

    const __nv_bfloat16* AH = (mode == 2) ? g_peH : g_hsH;
    const __nv_bfloat16* AL = (mode == 2) ? g_peL : g_hsL;
    const __nv_bfloat16* BH = g_WH[mode];
    const __nv_bfloat16* BL = g_WL[mode];

    const int lr = t >> 1, lc = t & 1;
    const __nv_bfloat16* gah = AH + (size_t)(bm + lr) * K + lc * 8;
    const __nv_bfloat16* gal = AL + (size_t)(bm + lr) * K + lc * 8;
    const __nv_bfloat16* gbh = BH + (size_t)(bn + lr) * K + lc * 8;
    const __nv_bfloat16* gbl = BL + (size_t)(bn + lr) * K + lc * 8;
    const uint32_t sb0 = (uint32_t)__cvta_generic_to_shared(smem);
    const uint32_t lun = (uint32_t)(UNIT(lr, lc) << 4);

    #pragma unroll
    for (int s = 0; s < 2; s++) {
        const uint32_t d = sb0 + s * STG + lun;
        cp16(d,         gah + s * 16);
        cp16(d + 4096,  gal + s * 16);
        cp16(d + 8192,  gbh + s * 16);
        cp16(d + 12288, gbl + s * 16);
        cp_commit();
    }

    uint32_t aoff[4], boff[4];
    {
        const int rr = (lane & 7) + ((lane >> 3) & 1) * 8;
        const int cc = lane >> 4;
        #pragma unroll
        for (int mi = 0; mi < 4; mi++)
            aoff[mi] = (uint32_t)(UNIT(wm * 64 + mi * 16 + rr, cc) << 4);
        const int l15 = lane & 15;
        #pragma unroll
        for (int ni = 0; ni < 4; ni++)
            boff[ni] = (uint32_t)(UNIT(wn * 32 + ni * 8 + (l15 & 7), l15 >> 3) << 4);
    }

    float acc[4][4][4] = {};
    for (int it = 0; it < NIT; ++it) {
        cp_wait<1>();
        __syncthreads();
        const int pf = it + 2;
        if (pf < NIT) {
            const uint32_t d = sb0 + (pf % 3) * STG + lun;
            cp16(d,         gah + pf * 16);
            cp16(d + 4096,  gal + pf * 16);
            cp16(d + 8192,  gbh + pf * 16);
            cp16(d + 12288, gbl + pf * 16);
        }
        cp_commit();

        const uint32_t base = sb0 + (it % 3) * STG;
        uint32_t bhf[4][2], blf[4][2];
        #pragma unroll
        for (int ni = 0; ni < 4; ni++) {
            ldsm_x2(bhf[ni], base + 8192  + boff[ni]);
            ldsm_x2(blf[ni], base + 12288 + boff[ni]);
        }
        #pragma unroll
        for (int mi = 0; mi < 4; mi++) {
            uint32_t ah[4], al[4];
            ldsm_x4(ah, base + aoff[mi]);
            ldsm_x4(al, base + 4096 + aoff[mi]);
            #pragma unroll
            for (int ni = 0; ni < 4; ni++) {
                MMA(acc[mi][ni], ah[0], ah[1], ah[2], ah[3], bhf[ni][0], bhf[ni][1]);
                MMA(acc[mi][ni], ah[0], ah[1], ah[2], ah[3], blf[ni][0], blf[ni][1]);
                MMA(acc[mi][ni], al[0], al[1], al[2], al[3], bhf[ni][0], bhf[ni][1]);
            }
        }
    }

    // ---- epilogue (runtime mode switch) ----
    const float* b1 = (mode == 0) ? bq : (mode == 1) ? bk : (mode == 3) ? bv : nullptr;
    #pragma unroll
    for (int mi = 0; mi < 4; mi++) {
        #pragma unroll
        for (int half = 0; half < 2; half++) {
            const int row = bm + wm * 64 + mi * 16 + g + half * 8;
            const int b = row >> 11, n = row & (NSEQ - 1);
            #pragma unroll
            for (int ni = 0; ni < 4; ni++) {
                const int col = bn + wn * 32 + ni * 8 + tg * 2;
                float v0 = acc[mi][ni][half * 2 + 0];
                float v1 = acc[mi][ni][half * 2 + 1];
                if (b1) { v0 += b1[col]; v1 += b1[col + 1]; }
                const int h = col >> 6, d = col & 63;
                const size_t base128 = (((size_t)(b * NH + h)) * NSEQ + n) * 128;
                if (mode == 0) {
                    uint32_t lo, hi;
                    hi = pack_split(v0 + pbu[h * 64 + d], v1 + pbu[h * 64 + d + 1], lo);
                    *(uint32_t*)&g_QQH[base128 + d] = hi;
                    *(uint32_t*)&g_QQL[base128 + d] = lo;
                    hi = pack_split(v0 + pbv[h * 64 + d], v1 + pbv[h * 64 + d + 1], lo);
                    *(uint32_t*)&g_QQH[base128 + 64 + d] = hi;
                    *(uint32_t*)&g_QQL[base128 + 64 + d] = lo;
                } else if (mode == 1) {
                    uint32_t lo, hi = pack_split(v0, v1, lo);
                    *(uint32_t*)&g_KKH[base128 + d] = hi;
                    *(uint32_t*)&g_KKL[base128 + d] = lo;
                } else if (mode == 2) {
                    uint32_t lo, hi = pack_split(v0, v1, lo);
                    *(uint32_t*)&g_KKH[base128 + 64 + d] = hi;
                    *(uint32_t*)&g_KKL[base128 + 64 + d] = lo;
                } else {
                    const size_t vb = (((size_t)(b * NH + h)) * ND + d) * NSEQ + n;
                    __nv_bfloat16 h0 = __float2bfloat16(v0);
                    __nv_bfloat16 l0 = __float2bfloat16(v0 - __bfloat162float(h0));
                    __nv_bfloat16 h1 = __float2bfloat16(v1);
                    __nv_bfloat16 l1 = __float2bfloat16(v1 - __bfloat162float(h1));
                    g_VH[vb] = h0;        g_VL[vb] = l0;
                    g_VH[vb + NSEQ] = h1; g_VL[vb + NSEQ] = l1;
                }
            }
        }
    }
}

// ============================================================================
// Out-projection: out = ctx @ Wo^T + bo (K=1024), fp32 output.
// ============================================================================
__global__ void __launch_bounds__(256, 2) gemm_out(
    const float* __restrict__ bo, float* __restrict__ out)
{
    constexpr int K   = 1024;
    constexpr int NIT = K / 16;
    constexpr int STG = 16384;
    __shared__ __align__(16) unsigned char smem[3 * STG];

    const int t = threadIdx.x, lane = t & 31, wid = t >> 5;
    const int g = lane >> 2, tg = lane & 3;
    const int wm = wid & 1, wn = wid >> 1;
    const int bm = blockIdx.y * 128, bn = blockIdx.x * 128;

    const int lr = t >> 1, lc = t & 1;
    const __nv_bfloat16* gah = g_ctxH + (size_t)(bm + lr) * K + lc * 8;
    const __nv_bfloat16* gal = g_ctxL + (size_t)(bm + lr) * K + lc * 8;
    const __nv_bfloat16* gbh = g_WH[4] + (size_t)(bn + lr) * K + lc * 8;
    const __nv_bfloat16* gbl = g_WL[4] + (size_t)(bn + lr) * K + lc * 8;
    const uint32_t sb0 = (uint32_t)__cvta_generic_to_shared(smem);
    const uint32_t lun = (uint32_t)(UNIT(lr, lc) << 4);

    #pragma unroll
    for (int s = 0; s < 2; s++) {
        const uint32_t d = sb0 + s * STG + lun;
        cp16(d,         gah + s * 16);
        cp16(d + 4096,  gal + s * 16);
        cp16(d + 8192,  gbh + s * 16);
        cp16(d + 12288, gbl + s * 16);
        cp_commit();
    }

    uint32_t aoff[4], boff[4];
    {
        const int rr = (lane & 7) + ((lane >> 3) & 1) * 8;
        const int cc = lane >> 4;
        #pragma unroll
        for (int mi = 0; mi < 4; mi++)
            aoff[mi] = (uint32_t)(UNIT(wm * 64 + mi * 16 + rr, cc) << 4);
        const int l15 = lane & 15;
        #pragma unroll
        for (int ni = 0; ni < 4; ni++)
            boff[ni] = (uint32_t)(UNIT(wn * 32 + ni * 8 + (l15 & 7), l15 >> 3) << 4);
    }

    float acc[4][4][4] = {};
    for (int it = 0; it < NIT; ++it) {
        cp_wait<1>();
        __syncthreads();
        const int pf = it + 2;
        if (pf < NIT) {
            const uint32_t d = sb0 + (pf % 3) * STG + lun;
            cp16(d,         gah + pf * 16);
            cp16(d + 4096,  gal + pf * 16);
            cp16(d + 8192,  gbh + pf * 16);
            cp16(d + 12288, gbl + pf * 16);
        }
        cp_commit();

        const uint32_t base = sb0 + (it % 3) * STG;
        uint32_t bhf[4][2], blf[4][2];
        #pragma unroll
        for (int ni = 0; ni < 4; ni++) {
            ldsm_x2(bhf[ni], base + 8192  + boff[ni]);
            ldsm_x2(blf[ni], base + 12288 + boff[ni]);
        }
        #pragma unroll
        for (int mi = 0; mi < 4; mi++) {
            uint32_t ah[4], al[4];
            ldsm_x4(ah, base + aoff[mi]);
            ldsm_x4(al, base + 4096 + aoff[mi]);
            #pragma unroll
            for (int ni = 0; ni < 4; ni++) {
                MMA(acc[mi][ni], ah[0], ah[1], ah[2], ah[3], bhf[ni][0], bhf[ni][1]);
                MMA(acc[mi][ni], ah[0], ah[1], ah[2], ah[3], blf[ni][0], blf[ni][1]);
                MMA(acc[mi][ni], al[0], al[1], al[2], al[3], bhf[ni][0], bhf[ni][1]);
            }
        }
    }

    #pragma unroll
    for (int mi = 0; mi < 4; mi++) {
        #pragma unroll
        for (int half = 0; half < 2; half++) {
            const int row = bm + wm * 64 + mi * 16 + g + half * 8;
            #pragma unroll
            for (int ni = 0; ni < 4; ni++) {
                const int col = bn + wn * 32 + ni * 8 + tg * 2;
                *(float2*)&out[(size_t)row * NC + col] =
                    make_float2(acc[mi][ni][half * 2 + 0] + bo[col],
                                acc[mi][ni][half * 2 + 1] + bo[col + 1]);
            }
        }
    }
}

// ============================================================================
// Fused flash attention: Q fragments in registers; K,V double-buffered smem.
// smem: Kh/Kl x2 (128KB) + Vh/Vl x2 (64KB) = 192KB.
// ============================================================================
__device__ __forceinline__ void load_K(uint32_t uK,
    const __nv_bfloat16* gh, const __nv_bfloat16* gl, int qr, int qc0)
{
    #pragma unroll
    for (int c = 0; c < 8; c++) {
        const int ch = qc0 + c;
        cp16(uK +         (uint32_t)(SWZ(qr, ch) << 4), gh + (size_t)qr * 128 + ch * 8);
        cp16(uK + 32768 + (uint32_t)(SWZ(qr, ch) << 4), gl + (size_t)qr * 128 + ch * 8);
    }
}
__device__ __forceinline__ void load_V(uint32_t uV,
    const __nv_bfloat16* gh, const __nv_bfloat16* gl, int vr, int vc0)
{
    #pragma unroll
    for (int c = 0; c < 4; c++) {
        const int ch = vc0 + c;
        cp16(uV +         (uint32_t)(SWZ(vr, ch) << 4), gh + (size_t)vr * NSEQ + ch * 8);
        cp16(uV + 16384 + (uint32_t)(SWZ(vr, ch) << 4), gl + (size_t)vr * NSEQ + ch * 8);
    }
}

__global__ void __launch_bounds__(256, 1) flash_kernel()
{
    extern __shared__ __align__(16) unsigned char sm[];
    const uint32_t sb = (uint32_t)__cvta_generic_to_shared(sm);
    // K buffers at sb + sel*65536 (hi at +0, lo at +32768)
    // V buffers at sb + 131072 + sel*32768 (hi at +0, lo at +16384)

    const int bh = blockIdx.y;
    const int bm = blockIdx.x * 128;
    const int t = threadIdx.x, lane = t & 31, wid = t >> 5;
    const int g = lane >> 2, tg = lane & 3;

    const __nv_bfloat16* QH = g_QQH + (size_t)bh * NSEQ * 128 + (size_t)bm * 128;
    const __nv_bfloat16* QL = g_QQL + (size_t)bh * NSEQ * 128 + (size_t)bm * 128;
    const __nv_bfloat16* KH = g_KKH + (size_t)bh * NSEQ * 128;
    const __nv_bfloat16* KL = g_KKL + (size_t)bh * NSEQ * 128;
    const __nv_bfloat16* VH = g_VH  + (size_t)bh * ND * NSEQ;
    const __nv_bfloat16* VL = g_VL  + (size_t)bh * ND * NSEQ;

    const int qr = t >> 1, qc0 = (t & 1) * 8;   // K loader
    const int vr = t >> 2, vc0 = (t & 3) * 4;   // V loader

    // prefetch K0,V0 (g0) and K1,V1 (g1)
    load_K(sb,          KH, KL, qr, qc0);
    load_V(sb + 131072, VH, VL, vr, vc0);
    cp_commit();
    load_K(sb + 65536,  KH + 128 * 128, KL + 128 * 128, qr, qc0);
    load_V(sb + 163840, VH + 128,       VL + 128,       vr, vc0);
    cp_commit();

    // ---- Q fragments -> registers (loop-invariant) ----
    uint32_t qfh[8][4], qfl[8][4];
    {
        const int r0 = wid * 16 + g;
        #pragma unroll
        for (int kb = 0; kb < 8; kb++) {
            const int k0 = kb * 16 + tg * 2;
            qfh[kb][0] = *(const uint32_t*)&QH[(size_t)r0 * 128 + k0];
            qfh[kb][1] = *(const uint32_t*)&QH[(size_t)(r0 + 8) * 128 + k0];
            qfh[kb][2] = *(const uint32_t*)&QH[(size_t)r0 * 128 + k0 + 8];
            qfh[kb][3] = *(const uint32_t*)&QH[(size_t)(r0 + 8) * 128 + k0 + 8];
            qfl[kb][0] = *(const uint32_t*)&QL[(size_t)r0 * 128 + k0];
            qfl[kb][1] = *(const uint32_t*)&QL[(size_t)(r0 + 8) * 128 + k0];
            qfl[kb][2] = *(const uint32_t*)&QL[(size_t)r0 * 128 + k0 + 8];
            qfl[kb][3] = *(const uint32_t*)&QL[(size_t)(r0 + 8) * 128 + k0 + 8];
        }
    }

    const int l15 = lane & 15;
    const int brow = (l15 & 7) + (lane >> 4) * 8;
    const int bch  = l15 >> 3;

    float m_r[2] = {-1e30f, -1e30f}, l_r[2] = {0.f, 0.f};
    float o_acc[8][4] = {};

    for (int kt = 0; kt < 16; kt++) {
        // K[kt], V[kt] both guaranteed after this wait (prefetch distance 2)
        if (kt == 0)      cp_wait<1>();
        else if (kt == 1) cp_wait<2>();
        else              cp_wait<2>();
        __syncthreads();

        const uint32_t uK = sb + (kt & 1) * 65536;
        const uint32_t uV = sb + 131072 + (kt & 1) * 32768;

        // ---- S = Q @ K^T (bf16x3), Q from registers ----
        float acc[16][4] = {};
        #pragma unroll
        for (int kb = 0; kb < 8; kb++) {
            #pragma unroll
            for (int np = 0; np < 8; np++) {
                uint32_t kh4[4], kl4[4];
                ldsm_x4(kh4, uK +         (uint32_t)(SWZ(np * 16 + brow, kb * 2 + bch) << 4));
                ldsm_x4(kl4, uK + 32768 + (uint32_t)(SWZ(np * 16 + brow, kb * 2 + bch) << 4));
                MMA(acc[np * 2],     qfh[kb][0], qfh[kb][1], qfh[kb][2], qfh[kb][3], kh4[0], kh4[1]);
                MMA(acc[np * 2],     qfh[kb][0], qfh[kb][1], qfh[kb][2], qfh[kb][3], kl4[0], kl4[1]);
                MMA(acc[np * 2],     qfl[kb][0], qfl[kb][1], qfl[kb][2], qfl[kb][3], kh4[0], kh4[1]);
                MMA(acc[np * 2 + 1], qfh[kb][0], qfh[kb][1], qfh[kb][2], qfh[kb][3], kh4[2], kh4[3]);
                MMA(acc[np * 2 + 1], qfh[kb][0], qfh[kb][1], qfh[kb][2], qfh[kb][3], kl4[2], kl4[3]);
                MMA(acc[np * 2 + 1], qfl[kb][0], qfl[kb][1], qfl[kb][2], qfl[kb][3], kh4[2], kh4[3]);
            }
        }
        __syncthreads();       // all warps done reading K[kt] buffer
        if (kt + 2 < 16)
            load_K(uK, KH + (size_t)(kt + 2) * 128 * 128,
                       KL + (size_t)(kt + 2) * 128 * 128, qr, qc0);
        cp_commit();

        // ---- online softmax (registers) ----
        float mx0 = -1e30f, mx1 = -1e30f;
        #pragma unroll
        for (int ni = 0; ni < 16; ni++) {
            mx0 = fmaxf(mx0, fmaxf(acc[ni][0], acc[ni][1]));
            mx1 = fmaxf(mx1, fmaxf(acc[ni][2], acc[ni][3]));
        }
        mx0 *= ATT_SCALE; mx1 *= ATT_SCALE;
        mx0 = fmaxf(mx0, __shfl_xor_sync(0xFFFFFFFFu, mx0, 1));
        mx0 = fmaxf(mx0, __shfl_xor_sync(0xFFFFFFFFu, mx0, 2));
        mx1 = fmaxf(mx1, __shfl_xor_sync(0xFFFFFFFFu, mx1, 1));
        mx1 = fmaxf(mx1, __shfl_xor_sync(0xFFFFFFFFu, mx1, 2));
        const float mn0 = fmaxf(m_r[0], mx0), mn1 = fmaxf(m_r[1], mx1);
        const float c0 = __expf(m_r[0] - mn0), c1 = __expf(m_r[1] - mn1);
        m_r[0] = mn0; m_r[1] = mn1;
        float s0 = 0.f, s1 = 0.f;
        #pragma unroll
        for (int ni = 0; ni < 16; ni++) {
            acc[ni][0] = __expf(fmaf(acc[ni][0], ATT_SCALE, -mn0)); s0 += acc[ni][0];
            acc[ni][1] = __expf(fmaf(acc[ni][1], ATT_SCALE, -mn0)); s0 += acc[ni][1];
            acc[ni][2] = __expf(fmaf(acc[ni][2], ATT_SCALE, -mn1)); s1 += acc[ni][2];
            acc[ni][3] = __expf(fmaf(acc[ni][3], ATT_SCALE, -mn1)); s1 += acc[ni][3];
        }
        s0 += __shfl_xor_sync(0xFFFFFFFFu, s0, 1);
        s0 += __shfl_xor_sync(0xFFFFFFFFu, s0, 2);
        s1 += __shfl_xor_sync(0xFFFFFFFFu, s1, 1);
        s1 += __shfl_xor_sync(0xFFFFFFFFu, s1, 2);
        l_r[0] = l_r[0] * c0 + s0;
        l_r[1] = l_r[1] * c1 + s1;
        #pragma unroll
        for (int nj = 0; nj < 8; nj++) {
            o_acc[nj][0] *= c0; o_acc[nj][1] *= c0;
            o_acc[nj][2] *= c1; o_acc[nj][3] *= c1;
        }

        // ---- O += P @ V (V already resident; no wait) ----
        #pragma unroll
        for (int kb = 0; kb < 8; kb++) {
            uint32_t ph[4], pl[4];
            ph[0] = pack_split(acc[2 * kb][0],     acc[2 * kb][1],     pl[0]);
            ph[1] = pack_split(acc[2 * kb][2],     acc[2 * kb][3],     pl[1]);
            ph[2] = pack_split(acc[2 * kb + 1][0], acc[2 * kb + 1][1], pl[2]);
            ph[3] = pack_split(acc[2 * kb + 1][2], acc[2 * kb + 1][3], pl[3]);
            #pragma unroll
            for (int np = 0; np < 4; np++) {
                uint32_t vh4[4], vl4[4];
                ldsm_x4(vh4, uV +         (uint32_t)(SWZ(np * 16 + brow, kb * 2 + bch) << 4));
                ldsm_x4(vl4, uV + 16384 + (uint32_t)(SWZ(np * 16 + brow, kb * 2 + bch) << 4));
                MMA(o_acc[np * 2],     ph[0], ph[1], ph[2], ph[3], vh4[0], vh4[1]);
                MMA(o_acc[np * 2],     pl[0], pl[1], pl[2], pl[3], vh4[0], vh4[1]);
                MMA(o_acc[np * 2],     ph[0], ph[1], ph[2], ph[3], vl4[0], vl4[1]);
                MMA(o_acc[np * 2 + 1], ph[0], ph[1], ph[2], ph[3], vh4[2], vh4[3]);
                MMA(o_acc[np * 2 + 1], pl[0], pl[1], pl[2], pl[3], vh4[2], vh4[3]);
                MMA(o_acc[np * 2 + 1], ph[0], ph[1], ph[2], ph[3], vl4[2], vl4[3]);
            }
        }
        __syncthreads();       // all warps done reading V[kt] buffer
        if (kt + 2 < 16)
            load_V(uV, VH + (size_t)(kt + 2) * 128,
                       VL + (size_t)(kt + 2) * 128, vr, vc0);
        cp_commit();
    }

    // ---- epilogue ----
    const int b = bh >> 4, h = bh & 15;
    const float inv0 = 1.f / l_r[0], inv1 = 1.f / l_r[1];
    const int row0 = bm + wid * 16 + g;
    #pragma unroll
    for (int nj = 0; nj < 8; nj++) {
        const int d = h * 64 + nj * 8 + tg * 2;
        uint32_t lo, hi;
        const size_t i0 = ((size_t)(b * NSEQ + row0)) * NC + d;
        hi = pack_split(o_acc[nj][0] * inv0, o_acc[nj][1] * inv0, lo);
        *(uint32_t*)&g_ctxH[i0] = hi; *(uint32_t*)&g_ctxL[i0] = lo;
        const size_t i1 = ((size_t)(b * NSEQ + row0 + 8)) * NC + d;
        hi = pack_split(o_acc[nj][2] * inv1, o_acc[nj][3] * inv1, lo);
        *(uint32_t*)&g_ctxH[i1] = hi; *(uint32_t*)&g_ctxL[i1] = lo;
    }
}

// ============================================================================
extern "C" void kernel_launch(void* const* d_in, const int* in_sizes, int n_in,
                              void* d_out, int out_size)
{
    const float* hs   = (const float*)d_in[0];
    const float* pe   = (const float*)d_in[1];
    const float* Wq   = (const float*)d_in[2];
    const float* bq   = (const float*)d_in[3];
    const float* Wk   = (const float*)d_in[4];
    const float* bk   = (const float*)d_in[5];
    const float* Wv   = (const float*)d_in[6];
    const float* bv   = (const float*)d_in[7];
    const float* Wpos = (const float*)d_in[8];
    const float* pbu  = (const float*)d_in[9];
    const float* pbv  = (const float*)d_in[10];
    const float* Wo   = (const float*)d_in[11];
    const float* bo   = (const float*)d_in[12];
    float* out = (float*)d_out;

    static int smem_set = 0;
    if (!smem_set) {
        cudaFuncSetAttribute(flash_kernel,
                             cudaFuncAttributeMaxDynamicSharedMemorySize, 196608);
        smem_set = 1;
    }

    constexpr int A = NB * NSEQ * NC / 4;
    constexpr int W = NC * NC / 4;
    split_all<<<(2 * A + 5 * W) / 256, 256>>>(
        (const float4*)hs, (const float4*)pe, (const float4*)Wq,
        (const float4*)Wk, (const float4*)Wpos, (const float4*)Wv,
        (const float4*)Wo);

    gemm_qkvp<<<dim3(NC / 128, (NB * NSEQ) / 128, 4), 256>>>(bq, bk, bv, pbu, pbv);

    flash_kernel<<<dim3(NSEQ / 128, NB * NH), 256, 196608>>>();

    gemm_out<<<dim3(NC / 128, (NB * NSEQ) / 128), 256>>>(bo, out);
}

// round 9
// speedup vs baseline: 3.0909x; 1.0007x over previous
#include <cuda_runtime.h>
#include <cuda_bf16.h>
#include <stdint.h>

#define NB   2
#define NSEQ 2048
#define NC   1024
#define NH   16
#define ND   64
#define ATT_SCALE 0.125f

// ---- bf16 hi/lo split scratch (device globals) ----
__device__ __nv_bfloat16 g_hsH[(size_t)NB*NSEQ*NC],  g_hsL[(size_t)NB*NSEQ*NC];
__device__ __nv_bfloat16 g_peH[(size_t)NB*NSEQ*NC],  g_peL[(size_t)NB*NSEQ*NC];
__device__ __nv_bfloat16 g_WH[5][(size_t)NC*NC],     g_WL[5][(size_t)NC*NC]; // q,k,pos,v,o
__device__ __nv_bfloat16 g_QQH[(size_t)NB*NH*NSEQ*128], g_QQL[(size_t)NB*NH*NSEQ*128];
__device__ __nv_bfloat16 g_KKH[(size_t)NB*NH*NSEQ*128], g_KKL[(size_t)NB*NH*NSEQ*128];
__device__ __nv_bfloat16 g_VH[(size_t)NB*NH*ND*NSEQ],   g_VL[(size_t)NB*NH*ND*NSEQ]; // (B,H,D,N)
__device__ __nv_bfloat16 g_ctxH[(size_t)NB*NSEQ*NC],    g_ctxL[(size_t)NB*NSEQ*NC];

// ---- helpers ----
__device__ __forceinline__ uint32_t pack_split(float x, float y, uint32_t& lo_out) {
    __nv_bfloat162 h = __floats2bfloat162_rn(x, y);
    __nv_bfloat162 l = __floats2bfloat162_rn(x - __bfloat162float(h.x),
                                             y - __bfloat162float(h.y));
    lo_out = *reinterpret_cast<uint32_t*>(&l);
    return *reinterpret_cast<uint32_t*>(&h);
}
__device__ __forceinline__ void cp16(uint32_t dst, const void* src) {
    asm volatile("cp.async.cg.shared.global [%0], [%1], 16;" :: "r"(dst), "l"(src));
}
__device__ __forceinline__ void cp_commit() {
    asm volatile("cp.async.commit_group;" ::: "memory");
}
template<int N> __device__ __forceinline__ void cp_wait() {
    asm volatile("cp.async.wait_group %0;" :: "n"(N) : "memory");
}
__device__ __forceinline__ void ldsm_x4(uint32_t* r, uint32_t a) {
    asm volatile("ldmatrix.sync.aligned.m8n8.x4.shared.b16 {%0,%1,%2,%3}, [%4];"
                 : "=r"(r[0]), "=r"(r[1]), "=r"(r[2]), "=r"(r[3]) : "r"(a));
}
__device__ __forceinline__ void ldsm_x2(uint32_t* r, uint32_t a) {
    asm volatile("ldmatrix.sync.aligned.m8n8.x2.shared.b16 {%0,%1}, [%2];"
                 : "=r"(r[0]), "=r"(r[1]) : "r"(a));
}

#define MMA(d, A0, A1, A2, A3, B0, B1)                                   \
    asm volatile("mma.sync.aligned.m16n8k16.row.col.f32.bf16.bf16.f32 "  \
                 "{%0,%1,%2,%3},{%4,%5,%6,%7},{%8,%9},{%0,%1,%2,%3};"    \
                 : "+f"(d[0]), "+f"(d[1]), "+f"(d[2]), "+f"(d[3])        \
                 : "r"(A0), "r"(A1), "r"(A2), "r"(A3), "r"(B0), "r"(B1))

// 64B-row tiles (32 bf16 per row, 4 chunks of 16B) used by gemm  (SW64 pattern)
__device__ __forceinline__ int UNIT32(int r, int c) { return r * 4 + (c ^ ((r >> 1) & 3)); }
// 256B-row tiles (128 bf16/row, 16 chunks of 16B) used by flash
__device__ __forceinline__ int SWZ(int r, int c) { return r * 16 + (c ^ (r & 7)); }

// ============================================================================
// Merged pre-pass: split ALL fp32 inputs into bf16 hi/lo planes.
// ============================================================================
__global__ void __launch_bounds__(256) split_all(
    const float4* __restrict__ hs, const float4* __restrict__ pe,
    const float4* __restrict__ wq, const float4* __restrict__ wk,
    const float4* __restrict__ wpos, const float4* __restrict__ wv,
    const float4* __restrict__ wo)
{
    const int i = blockIdx.x * 256 + threadIdx.x;
    constexpr int A = NB * NSEQ * NC / 4;
    constexpr int W = NC * NC / 4;
    const float4* src;
    __nv_bfloat16 *H, *L;
    int off;
    if (i < A)            { src = hs; off = i;     H = g_hsH; L = g_hsL; }
    else if (i < 2 * A)   { src = pe; off = i - A; H = g_peH; L = g_peL; }
    else {
        const int j = i - 2 * A;
        const int w = j >> 18;
        off = j & (W - 1);
        switch (w) {
            case 0:  src = wq;   break;
            case 1:  src = wk;   break;
            case 2:  src = wpos; break;
            case 3:  src = wv;   break;
            default: src = wo;   break;
        }
        H = g_WH[w]; L = g_WL[w];
    }
    const float4 v = src[off];
    uint32_t l0, l1;
    const uint32_t h0 = pack_split(v.x, v.y, l0);
    const uint32_t h1 = pack_split(v.z, v.w, l1);
    *(uint2*)(H + (size_t)off * 4) = make_uint2(h0, h1);
    *(uint2*)(L + (size_t)off * 4) = make_uint2(l0, l1);
}

// ============================================================================
// 128x128 bf16x3 GEMM, K=1024, BK=32 stages (3-deep, 96KB, 2 CTA/SM).
// KIND 0: q/k/pos/v projections (mode = blockIdx.z). KIND 1: out-projection.
// Stage layout: Ah 8K | Al 8K | Bh 8K | Bl 8K  (rows of 64B, SW64 swizzle).
// ============================================================================
template<int KIND>
__global__ void __launch_bounds__(256, 2) gemm_bf16(
    const float* __restrict__ b1, const float* __restrict__ bk,
    const float* __restrict__ bv, const float* __restrict__ pbu,
    const float* __restrict__ pbv, float* __restrict__ out)
{
    constexpr int NIT = 32;          // K=1024 / 32
    constexpr int STG = 32768;
    extern __shared__ __align__(16) unsigned char smem[];
    const uint32_t sb0 = (uint32_t)__cvta_generic_to_shared(smem);

    const int mode = (KIND == 0) ? blockIdx.z : 4;
    const int t = threadIdx.x, lane = t & 31, wid = t >> 5;
    const int g = lane >> 2, tg = lane & 3;
    const int wm = wid & 1, wn = wid >> 1;
    const int bm = blockIdx.y * 128, bn = blockIdx.x * 128;

    const __nv_bfloat16 *AH, *AL;
    if (KIND == 1)        { AH = g_ctxH; AL = g_ctxL; }
    else if (mode == 2)   { AH = g_peH;  AL = g_peL; }
    else                  { AH = g_hsH;  AL = g_hsL; }
    const __nv_bfloat16* BH = g_WH[mode];
    const __nv_bfloat16* BL = g_WL[mode];

    // loaders: row 0..127, 2 chunks of 16B per plane per thread
    const int row = t >> 1;
    const int ch0 = (t & 1) * 2;
    const __nv_bfloat16* gah = AH + (size_t)(bm + row) * 1024;
    const __nv_bfloat16* gal = AL + (size_t)(bm + row) * 1024;
    const __nv_bfloat16* gbh = BH + (size_t)(bn + row) * 1024;
    const __nv_bfloat16* gbl = BL + (size_t)(bn + row) * 1024;
    uint32_t dsw[2];
    dsw[0] = (uint32_t)(UNIT32(row, ch0)     << 4);
    dsw[1] = (uint32_t)(UNIT32(row, ch0 + 1) << 4);

    #define LOAD_STAGE(buf, slice)                                          \
    {   const uint32_t st_ = sb0 + (buf) * STG;                              \
        _Pragma("unroll")                                                    \
        for (int j = 0; j < 2; j++) {                                        \
            const int e_ = (slice) * 32 + (ch0 + j) * 8;                     \
            cp16(st_ +         dsw[j], gah + e_);                            \
            cp16(st_ + 8192  + dsw[j], gal + e_);                            \
            cp16(st_ + 16384 + dsw[j], gbh + e_);                            \
            cp16(st_ + 24576 + dsw[j], gbl + e_);                            \
        } }

    LOAD_STAGE(0, 0); cp_commit();
    LOAD_STAGE(1, 1); cp_commit();

    uint32_t aoff[4][2], boff[4][2];
    {
        const int rr = (lane & 7) + ((lane >> 3) & 1) * 8;
        const int cc = lane >> 4;
        const int l15 = lane & 15;
        #pragma unroll
        for (int kb = 0; kb < 2; kb++) {
            #pragma unroll
            for (int mi = 0; mi < 4; mi++)
                aoff[mi][kb] = (uint32_t)(UNIT32(wm * 64 + mi * 16 + rr, 2 * kb + cc) << 4);
            #pragma unroll
            for (int ni = 0; ni < 4; ni++)
                boff[ni][kb] = (uint32_t)(UNIT32(wn * 32 + ni * 8 + (l15 & 7),
                                                 2 * kb + (l15 >> 3)) << 4);
        }
    }

    float acc[4][4][4] = {};
    for (int it = 0; it < NIT; ++it) {
        cp_wait<1>();
        __syncthreads();
        if (it + 2 < NIT) LOAD_STAGE((it + 2) % 3, it + 2);
        cp_commit();

        const uint32_t base = sb0 + (it % 3) * STG;
        #pragma unroll
        for (int kb = 0; kb < 2; kb++) {
            uint32_t bhf[4][2], blf[4][2];
            #pragma unroll
            for (int ni = 0; ni < 4; ni++) {
                ldsm_x2(bhf[ni], base + 16384 + boff[ni][kb]);
                ldsm_x2(blf[ni], base + 24576 + boff[ni][kb]);
            }
            #pragma unroll
            for (int mi = 0; mi < 4; mi++) {
                uint32_t ah[4], al[4];
                ldsm_x4(ah, base +        aoff[mi][kb]);
                ldsm_x4(al, base + 8192 + aoff[mi][kb]);
                #pragma unroll
                for (int ni = 0; ni < 4; ni++) {
                    MMA(acc[mi][ni], ah[0], ah[1], ah[2], ah[3], bhf[ni][0], bhf[ni][1]);
                    MMA(acc[mi][ni], ah[0], ah[1], ah[2], ah[3], blf[ni][0], blf[ni][1]);
                    MMA(acc[mi][ni], al[0], al[1], al[2], al[3], bhf[ni][0], bhf[ni][1]);
                }
            }
        }
    }

    // ---- epilogue ----
    #pragma unroll
    for (int mi = 0; mi < 4; mi++) {
        #pragma unroll
        for (int half = 0; half < 2; half++) {
            const int grow = bm + wm * 64 + mi * 16 + g + half * 8;
            const int b_ = grow >> 11, n_ = grow & (NSEQ - 1);
            #pragma unroll
            for (int ni = 0; ni < 4; ni++) {
                const int col = bn + wn * 32 + ni * 8 + tg * 2;
                float v0 = acc[mi][ni][half * 2 + 0];
                float v1 = acc[mi][ni][half * 2 + 1];
                if (KIND == 1) {
                    *(float2*)&out[(size_t)grow * NC + col] =
                        make_float2(v0 + b1[col], v1 + b1[col + 1]);
                    continue;
                }
                const int h = col >> 6, d = col & 63;
                const size_t base128 = (((size_t)(b_ * NH + h)) * NSEQ + n_) * 128;
                if (mode == 0) {
                    v0 += b1[col]; v1 += b1[col + 1];
                    uint32_t lo, hi;
                    hi = pack_split(v0 + pbu[h * 64 + d], v1 + pbu[h * 64 + d + 1], lo);
                    *(uint32_t*)&g_QQH[base128 + d] = hi;
                    *(uint32_t*)&g_QQL[base128 + d] = lo;
                    hi = pack_split(v0 + pbv[h * 64 + d], v1 + pbv[h * 64 + d + 1], lo);
                    *(uint32_t*)&g_QQH[base128 + 64 + d] = hi;
                    *(uint32_t*)&g_QQL[base128 + 64 + d] = lo;
                } else if (mode == 1) {
                    v0 += bk[col]; v1 += bk[col + 1];
                    uint32_t lo, hi = pack_split(v0, v1, lo);
                    *(uint32_t*)&g_KKH[base128 + d] = hi;
                    *(uint32_t*)&g_KKL[base128 + d] = lo;
                } else if (mode == 2) {
                    uint32_t lo, hi = pack_split(v0, v1, lo);
                    *(uint32_t*)&g_KKH[base128 + 64 + d] = hi;
                    *(uint32_t*)&g_KKL[base128 + 64 + d] = lo;
                } else {
                    v0 += bv[col]; v1 += bv[col + 1];
                    const size_t vb = (((size_t)(b_ * NH + h)) * ND + d) * NSEQ + n_;
                    __nv_bfloat16 h0 = __float2bfloat16(v0);
                    __nv_bfloat16 l0 = __float2bfloat16(v0 - __bfloat162float(h0));
                    __nv_bfloat16 h1 = __float2bfloat16(v1);
                    __nv_bfloat16 l1 = __float2bfloat16(v1 - __bfloat162float(h1));
                    g_VH[vb] = h0;        g_VL[vb] = l0;
                    g_VH[vb + NSEQ] = h1; g_VL[vb + NSEQ] = l1;
                }
            }
        }
    }
}

// ============================================================================
// Fused flash attention: Q frags in registers; K,V double-buffered (192KB);
// one commit group per iter; exp interleaved with PV MMAs.
// ============================================================================
__device__ __forceinline__ void load_K(uint32_t uK,
    const __nv_bfloat16* gh, const __nv_bfloat16* gl, int qr, int qc0)
{
    #pragma unroll
    for (int c = 0; c < 8; c++) {
        const int ch = qc0 + c;
        cp16(uK +         (uint32_t)(SWZ(qr, ch) << 4), gh + (size_t)qr * 128 + ch * 8);
        cp16(uK + 32768 + (uint32_t)(SWZ(qr, ch) << 4), gl + (size_t)qr * 128 + ch * 8);
    }
}
__device__ __forceinline__ void load_V(uint32_t uV,
    const __nv_bfloat16* gh, const __nv_bfloat16* gl, int vr, int vc0)
{
    #pragma unroll
    for (int c = 0; c < 4; c++) {
        const int ch = vc0 + c;
        cp16(uV +         (uint32_t)(SWZ(vr, ch) << 4), gh + (size_t)vr * NSEQ + ch * 8);
        cp16(uV + 16384 + (uint32_t)(SWZ(vr, ch) << 4), gl + (size_t)vr * NSEQ + ch * 8);
    }
}

__global__ void __launch_bounds__(256, 1) flash_kernel()
{
    extern __shared__ __align__(16) unsigned char sm2[];
    const uint32_t sb = (uint32_t)__cvta_generic_to_shared(sm2);
    // K buffers at sb + sel*65536 ; V buffers at sb + 131072 + sel*32768

    const int bh = blockIdx.y;
    const int bm = blockIdx.x * 128;
    const int t = threadIdx.x, lane = t & 31, wid = t >> 5;
    const int g = lane >> 2, tg = lane & 3;

    const __nv_bfloat16* QH = g_QQH + (size_t)bh * NSEQ * 128 + (size_t)bm * 128;
    const __nv_bfloat16* QL = g_QQL + (size_t)bh * NSEQ * 128 + (size_t)bm * 128;
    const __nv_bfloat16* KH = g_KKH + (size_t)bh * NSEQ * 128;
    const __nv_bfloat16* KL = g_KKL + (size_t)bh * NSEQ * 128;
    const __nv_bfloat16* VH = g_VH  + (size_t)bh * ND * NSEQ;
    const __nv_bfloat16* VL = g_VL  + (size_t)bh * ND * NSEQ;

    const int qr = t >> 1, qc0 = (t & 1) * 8;
    const int vr = t >> 2, vc0 = (t & 3) * 4;

    // one commit group per (K,V) tile pair
    load_K(sb,          KH, KL, qr, qc0);
    load_V(sb + 131072, VH, VL, vr, vc0);
    cp_commit();
    load_K(sb + 65536,  KH + 128 * 128, KL + 128 * 128, qr, qc0);
    load_V(sb + 163840, VH + 128,       VL + 128,       vr, vc0);
    cp_commit();

    uint32_t qfh[8][4], qfl[8][4];
    {
        const int r0 = wid * 16 + g;
        #pragma unroll
        for (int kb = 0; kb < 8; kb++) {
            const int k0 = kb * 16 + tg * 2;
            qfh[kb][0] = *(const uint32_t*)&QH[(size_t)r0 * 128 + k0];
            qfh[kb][1] = *(const uint32_t*)&QH[(size_t)(r0 + 8) * 128 + k0];
            qfh[kb][2] = *(const uint32_t*)&QH[(size_t)r0 * 128 + k0 + 8];
            qfh[kb][3] = *(const uint32_t*)&QH[(size_t)(r0 + 8) * 128 + k0 + 8];
            qfl[kb][0] = *(const uint32_t*)&QL[(size_t)r0 * 128 + k0];
            qfl[kb][1] = *(const uint32_t*)&QL[(size_t)(r0 + 8) * 128 + k0];
            qfl[kb][2] = *(const uint32_t*)&QL[(size_t)r0 * 128 + k0 + 8];
            qfl[kb][3] = *(const uint32_t*)&QL[(size_t)(r0 + 8) * 128 + k0 + 8];
        }
    }

    const int l15 = lane & 15;
    const int brow = (l15 & 7) + (lane >> 4) * 8;
    const int bch  = l15 >> 3;

    float m_r[2] = {-1e30f, -1e30f}, l_r[2] = {0.f, 0.f};
    float o_acc[8][4] = {};

    for (int kt = 0; kt < 16; kt++) {
        cp_wait<1>();          // K[kt] + V[kt] complete (one group per tile pair)
        __syncthreads();

        const uint32_t uK = sb + (kt & 1) * 65536;
        const uint32_t uV = sb + 131072 + (kt & 1) * 32768;

        // ---- S = Q @ K^T (bf16x3), Q from registers ----
        float acc[16][4] = {};
        #pragma unroll
        for (int kb = 0; kb < 8; kb++) {
            #pragma unroll
            for (int np = 0; np < 8; np++) {
                uint32_t kh4[4], kl4[4];
                ldsm_x4(kh4, uK +         (uint32_t)(SWZ(np * 16 + brow, kb * 2 + bch) << 4));
                ldsm_x4(kl4, uK + 32768 + (uint32_t)(SWZ(np * 16 + brow, kb * 2 + bch) << 4));
                MMA(acc[np * 2],     qfh[kb][0], qfh[kb][1], qfh[kb][2], qfh[kb][3], kh4[0], kh4[1]);
                MMA(acc[np * 2],     qfh[kb][0], qfh[kb][1], qfh[kb][2], qfh[kb][3], kl4[0], kl4[1]);
                MMA(acc[np * 2],     qfl[kb][0], qfl[kb][1], qfl[kb][2], qfl[kb][3], kh4[0], kh4[1]);
                MMA(acc[np * 2 + 1], qfh[kb][0], qfh[kb][1], qfh[kb][2], qfh[kb][3], kh4[2], kh4[3]);
                MMA(acc[np * 2 + 1], qfh[kb][0], qfh[kb][1], qfh[kb][2], qfh[kb][3], kl4[2], kl4[3]);
                MMA(acc[np * 2 + 1], qfl[kb][0], qfl[kb][1], qfl[kb][2], qfl[kb][3], kh4[2], kh4[3]);
            }
        }

        // ---- row max + correction (critical path) ----
        float mx0 = -1e30f, mx1 = -1e30f;
        #pragma unroll
        for (int ni = 0; ni < 16; ni++) {
            mx0 = fmaxf(mx0, fmaxf(acc[ni][0], acc[ni][1]));
            mx1 = fmaxf(mx1, fmaxf(acc[ni][2], acc[ni][3]));
        }
        mx0 *= ATT_SCALE; mx1 *= ATT_SCALE;
        mx0 = fmaxf(mx0, __shfl_xor_sync(0xFFFFFFFFu, mx0, 1));
        mx0 = fmaxf(mx0, __shfl_xor_sync(0xFFFFFFFFu, mx0, 2));
        mx1 = fmaxf(mx1, __shfl_xor_sync(0xFFFFFFFFu, mx1, 1));
        mx1 = fmaxf(mx1, __shfl_xor_sync(0xFFFFFFFFu, mx1, 2));
        const float mn0 = fmaxf(m_r[0], mx0), mn1 = fmaxf(m_r[1], mx1);
        const float c0 = __expf(m_r[0] - mn0), c1 = __expf(m_r[1] - mn1);
        m_r[0] = mn0; m_r[1] = mn1;
        #pragma unroll
        for (int nj = 0; nj < 8; nj++) {
            o_acc[nj][0] *= c0; o_acc[nj][1] *= c0;
            o_acc[nj][2] *= c1; o_acc[nj][3] *= c1;
        }

        // ---- exp interleaved with PV MMAs; sum reduction deferred ----
        float s0 = 0.f, s1 = 0.f;
        auto exppair = [&](int p) {
            #pragma unroll
            for (int q = 0; q < 2; q++) {
                float* a = acc[2 * p + q];
                a[0] = __expf(fmaf(a[0], ATT_SCALE, -mn0)); s0 += a[0];
                a[1] = __expf(fmaf(a[1], ATT_SCALE, -mn0)); s0 += a[1];
                a[2] = __expf(fmaf(a[2], ATT_SCALE, -mn1)); s1 += a[2];
                a[3] = __expf(fmaf(a[3], ATT_SCALE, -mn1)); s1 += a[3];
            }
        };
        exppair(0);
        #pragma unroll
        for (int kb = 0; kb < 8; kb++) {
            uint32_t ph[4], pl[4];
            ph[0] = pack_split(acc[2 * kb][0],     acc[2 * kb][1],     pl[0]);
            ph[1] = pack_split(acc[2 * kb][2],     acc[2 * kb][3],     pl[1]);
            ph[2] = pack_split(acc[2 * kb + 1][0], acc[2 * kb + 1][1], pl[2]);
            ph[3] = pack_split(acc[2 * kb + 1][2], acc[2 * kb + 1][3], pl[3]);
            #pragma unroll
            for (int np = 0; np < 4; np++) {
                uint32_t vh4[4], vl4[4];
                ldsm_x4(vh4, uV +         (uint32_t)(SWZ(np * 16 + brow, kb * 2 + bch) << 4));
                ldsm_x4(vl4, uV + 16384 + (uint32_t)(SWZ(np * 16 + brow, kb * 2 + bch) << 4));
                MMA(o_acc[np * 2],     ph[0], ph[1], ph[2], ph[3], vh4[0], vh4[1]);
                MMA(o_acc[np * 2],     pl[0], pl[1], pl[2], pl[3], vh4[0], vh4[1]);
                MMA(o_acc[np * 2],     ph[0], ph[1], ph[2], ph[3], vl4[0], vl4[1]);
                MMA(o_acc[np * 2 + 1], ph[0], ph[1], ph[2], ph[3], vh4[2], vh4[3]);
                MMA(o_acc[np * 2 + 1], pl[0], pl[1], pl[2], pl[3], vh4[2], vh4[3]);
                MMA(o_acc[np * 2 + 1], ph[0], ph[1], ph[2], ph[3], vl4[2], vl4[3]);
            }
            if (kb < 7) exppair(kb + 1);
        }

        s0 += __shfl_xor_sync(0xFFFFFFFFu, s0, 1);
        s0 += __shfl_xor_sync(0xFFFFFFFFu, s0, 2);
        s1 += __shfl_xor_sync(0xFFFFFFFFu, s1, 1);
        s1 += __shfl_xor_sync(0xFFFFFFFFu, s1, 2);
        l_r[0] = l_r[0] * c0 + s0;
        l_r[1] = l_r[1] * c1 + s1;

        __syncthreads();       // all warps done reading K[kt],V[kt] buffers
        if (kt + 2 < 16) {
            load_K(uK, KH + (size_t)(kt + 2) * 128 * 128,
                       KL + (size_t)(kt + 2) * 128 * 128, qr, qc0);
            load_V(uV, VH + (size_t)(kt + 2) * 128,
                       VL + (size_t)(kt + 2) * 128, vr, vc0);
        }
        cp_commit();
    }

    // ---- epilogue ----
    const int b = bh >> 4, h = bh & 15;
    const float inv0 = 1.f / l_r[0], inv1 = 1.f / l_r[1];
    const int row0 = bm + wid * 16 + g;
    #pragma unroll
    for (int nj = 0; nj < 8; nj++) {
        const int d = h * 64 + nj * 8 + tg * 2;
        uint32_t lo, hi;
        const size_t i0 = ((size_t)(b * NSEQ + row0)) * NC + d;
        hi = pack_split(o_acc[nj][0] * inv0, o_acc[nj][1] * inv0, lo);
        *(uint32_t*)&g_ctxH[i0] = hi; *(uint32_t*)&g_ctxL[i0] = lo;
        const size_t i1 = ((size_t)(b * NSEQ + row0 + 8)) * NC + d;
        hi = pack_split(o_acc[nj][2] * inv1, o_acc[nj][3] * inv1, lo);
        *(uint32_t*)&g_ctxH[i1] = hi; *(uint32_t*)&g_ctxL[i1] = lo;
    }
}

// ============================================================================
extern "C" void kernel_launch(void* const* d_in, const int* in_sizes, int n_in,
                              void* d_out, int out_size)
{
    const float* hs   = (const float*)d_in[0];
    const float* pe   = (const float*)d_in[1];
    const float* Wq   = (const float*)d_in[2];
    const float* bq   = (const float*)d_in[3];
    const float* Wk   = (const float*)d_in[4];
    const float* bk   = (const float*)d_in[5];
    const float* Wv   = (const float*)d_in[6];
    const float* bv   = (const float*)d_in[7];
    const float* Wpos = (const float*)d_in[8];
    const float* pbu  = (const float*)d_in[9];
    const float* pbv  = (const float*)d_in[10];
    const float* Wo   = (const float*)d_in[11];
    const float* bo   = (const float*)d_in[12];
    float* out = (float*)d_out;

    constexpr int GEMM_SMEM = 3 * 32768;   // 98304
    static int smem_set = 0;
    if (!smem_set) {
        cudaFuncSetAttribute(flash_kernel,
                             cudaFuncAttributeMaxDynamicSharedMemorySize, 196608);
        cudaFuncSetAttribute(gemm_bf16<0>,
                             cudaFuncAttributeMaxDynamicSharedMemorySize, GEMM_SMEM);
        cudaFuncSetAttribute(gemm_bf16<1>,
                             cudaFuncAttributeMaxDynamicSharedMemorySize, GEMM_SMEM);
        smem_set = 1;
    }

    constexpr int A = NB * NSEQ * NC / 4;
    constexpr int W = NC * NC / 4;
    split_all<<<(2 * A + 5 * W) / 256, 256>>>(
        (const float4*)hs, (const float4*)pe, (const float4*)Wq,
        (const float4*)Wk, (const float4*)Wpos, (const float4*)Wv,
        (const float4*)Wo);

    gemm_bf16<0><<<dim3(NC / 128, (NB * NSEQ) / 128, 4), 256, GEMM_SMEM>>>(
        bq, bk, bv, pbu, pbv, nullptr);

    flash_kernel<<<dim3(NSEQ / 128, NB * NH), 256, 196608>>>();

    gemm_bf16<1><<<dim3(NC / 128, (NB * NSEQ) / 128, 1), 256, GEMM_SMEM>>>(
        bo, nullptr, nullptr, nullptr, nullptr, out);
}